// round 1
// baseline (speedup 1.0000x reference)
#include <cuda_runtime.h>

#define NN   10000
#define EE   160000
#define IND  256
#define H0D  512      // 4 heads * 128
#define EMBD 256
#define ETOT (EE + NN)

// ---------------- scratch (device globals; no allocations allowed) ------------
__device__ float d_wsum[NN];
__device__ int   d_cnt[NN];
__device__ int   d_rowptr[NN + 1];
__device__ int   d_fill[NN];
__device__ int   d_csrc[ETOT];
__device__ float d_cw[ETOT];
__device__ __align__(16) float d_xl0[(size_t)NN * H0D];
__device__ __align__(16) float d_xr0[(size_t)NN * H0D];
__device__ __align__(16) float d_h0 [(size_t)NN * H0D];
__device__ __align__(16) float d_xl1[(size_t)NN * EMBD];
__device__ __align__(16) float d_xr1[(size_t)NN * EMBD];
__device__ __align__(16) float d_skp[(size_t)NN * EMBD];

// ---------------- small utility kernels ---------------------------------------
__global__ void zero_init_kernel() {
    int i = blockIdx.x * blockDim.x + threadIdx.x;
    if (i < NN) { d_wsum[i] = 0.f; d_cnt[i] = 0; d_fill[i] = 0; }
}

__global__ void hist_kernel(const int* __restrict__ eidx, const float* __restrict__ ew) {
    int e = blockIdx.x * blockDim.x + threadIdx.x;
    if (e < EE) {
        int d = eidx[EE + e];            // dst row
        atomicAdd(&d_cnt[d], 1);
        atomicAdd(&d_wsum[d], ew[e]);
    }
}

// single-block exclusive scan over (cnt[i] + 1) -> d_rowptr
__global__ void scan_kernel() {
    __shared__ int sh[1024];
    const int CH = 10;                   // 1024*10 = 10240 >= NN
    int t = threadIdx.x;
    int base = t * CH;
    int loc[CH];
    int run = 0;
#pragma unroll
    for (int i = 0; i < CH; i++) {
        int idx = base + i;
        int c = (idx < NN) ? (d_cnt[idx] + 1) : 0;   // +1 self loop
        run += c;
        loc[i] = run;
    }
    sh[t] = run;
    __syncthreads();
    for (int off = 1; off < 1024; off <<= 1) {
        int v = (t >= off) ? sh[t - off] : 0;
        __syncthreads();
        sh[t] += v;
        __syncthreads();
    }
    int excl = sh[t] - run;
#pragma unroll
    for (int i = 0; i < CH; i++) {
        int idx = base + i;
        if (idx < NN) d_rowptr[idx + 1] = excl + loc[i];
    }
    if (t == 0) d_rowptr[0] = 0;
}

__global__ void scatter_kernel(const int* __restrict__ eidx, const float* __restrict__ ew) {
    int e = blockIdx.x * blockDim.x + threadIdx.x;
    if (e >= ETOT) return;
    int s, d; float w;
    if (e < EE) {
        s = eidx[e]; d = eidx[EE + e]; w = ew[e];
    } else {
        int n = e - EE;
        s = n; d = n;
        int c = d_cnt[n];
        w = (c > 0) ? (d_wsum[n] / (float)c) : 0.f;   // fill_value='mean'
    }
    int pos = d_rowptr[d] + atomicAdd(&d_fill[d], 1);
    d_csrc[pos] = s;
    d_cw[pos]   = w;
}

// ---------------- SGEMM: C[M,N] = A[M,K] @ B[K,N] + bias[N] --------------------
// BM=BN=128, BK=8, 256 threads, 8x8 per thread.
__global__ __launch_bounds__(256, 2)
void sgemm_bias(const float* __restrict__ A, const float* __restrict__ B,
                const float* __restrict__ bias, float* __restrict__ C,
                int M, int K, int N) {
    __shared__ float As[8][128];
    __shared__ float Bs[8][128];
    int tid = threadIdx.x;
    int tx = tid & 15, ty = tid >> 4;
    int m0 = blockIdx.y * 128, n0 = blockIdx.x * 128;

    float acc[8][8];
#pragma unroll
    for (int i = 0; i < 8; i++)
#pragma unroll
        for (int j = 0; j < 8; j++) acc[i][j] = 0.f;

    int arow = tid >> 1, acol = (tid & 1) * 4;
    int brow = tid >> 5, bcol = (tid & 31) * 4;
    int gm = m0 + arow;

    for (int k0 = 0; k0 < K; k0 += 8) {
        float4 a4 = make_float4(0.f, 0.f, 0.f, 0.f);
        if (gm < M) a4 = *(const float4*)(A + (size_t)gm * K + k0 + acol);
        As[acol + 0][arow] = a4.x;
        As[acol + 1][arow] = a4.y;
        As[acol + 2][arow] = a4.z;
        As[acol + 3][arow] = a4.w;
        float4 b4 = *(const float4*)(B + (size_t)(k0 + brow) * N + n0 + bcol);
        *(float4*)&Bs[brow][bcol] = b4;
        __syncthreads();
#pragma unroll
        for (int k = 0; k < 8; k++) {
            float ar[8], br[8];
            *(float4*)&ar[0] = *(const float4*)&As[k][ty * 8];
            *(float4*)&ar[4] = *(const float4*)&As[k][ty * 8 + 4];
            *(float4*)&br[0] = *(const float4*)&Bs[k][tx * 8];
            *(float4*)&br[4] = *(const float4*)&Bs[k][tx * 8 + 4];
#pragma unroll
            for (int i = 0; i < 8; i++)
#pragma unroll
                for (int j = 0; j < 8; j++)
                    acc[i][j] += ar[i] * br[j];
        }
        __syncthreads();
    }
#pragma unroll
    for (int i = 0; i < 8; i++) {
        int m = m0 + ty * 8 + i;
        if (m < M) {
#pragma unroll
            for (int j = 0; j < 8; j++)
                C[(size_t)m * N + n0 + tx * 8 + j] = acc[i][j] + bias[n0 + tx * 8 + j];
        }
    }
}

// ---------------- GAT layer 0: 4 heads x 128, block per node -------------------
__device__ __forceinline__ float lrelu(float v) { return v >= 0.f ? v : 0.2f * v; }

__global__ __launch_bounds__(128)
void gat0_kernel(const float* __restrict__ We0, const float* __restrict__ att0,
                 const float* __restrict__ bias0, const float* __restrict__ prelu0) {
    int n = blockIdx.x;
    int lane = threadIdx.x & 31;
    int h = threadIdx.x >> 5;
    int c = h * 128 + lane * 4;

    float4 we = *(const float4*)(We0 + c);
    float4 at = *(const float4*)(att0 + c);          // att0[h,:] linear = h*128+c
    float4 xr = *(const float4*)(d_xr0 + (size_t)n * H0D + c);

    int rs = d_rowptr[n], re = d_rowptr[n + 1];
    float m = -1e30f, s = 0.f;
    float4 acc = make_float4(0.f, 0.f, 0.f, 0.f);

    for (int e = rs; e < re; e++) {
        int src = d_csrc[e];
        float w = d_cw[e];
        float4 xl = *(const float4*)(d_xl0 + (size_t)src * H0D + c);
        float vx = lrelu(xl.x + xr.x + w * we.x);
        float vy = lrelu(xl.y + xr.y + w * we.y);
        float vz = lrelu(xl.z + xr.z + w * we.z);
        float vw = lrelu(xl.w + xr.w + w * we.w);
        float part = vx * at.x + vy * at.y + vz * at.z + vw * at.w;
#pragma unroll
        for (int off = 16; off; off >>= 1)
            part += __shfl_xor_sync(0xffffffffu, part, off);
        float nm = fmaxf(m, part);
        float corr = __expf(m - nm);
        float p = __expf(part - nm);
        s = s * corr + p;
        acc.x = acc.x * corr + p * xl.x;
        acc.y = acc.y * corr + p * xl.y;
        acc.z = acc.z * corr + p * xl.z;
        acc.w = acc.w * corr + p * xl.w;
        m = nm;
    }
    float inv = 1.f / (s + 1e-16f);
    float4 b = *(const float4*)(bias0 + c);
    float4 pr = *(const float4*)(prelu0 + c);
    float ox = acc.x * inv + b.x; ox = ox >= 0.f ? ox : pr.x * ox;
    float oy = acc.y * inv + b.y; oy = oy >= 0.f ? oy : pr.y * oy;
    float oz = acc.z * inv + b.z; oz = oz >= 0.f ? oz : pr.z * oz;
    float ow = acc.w * inv + b.w; ow = ow >= 0.f ? ow : pr.w * ow;
    *(float4*)(d_h0 + (size_t)n * H0D + c) = make_float4(ox, oy, oz, ow);
}

// ---------------- GAT layer 1: 1 head x 256, warp per node ---------------------
__global__ __launch_bounds__(256)
void gat1_kernel(const float* __restrict__ We1, const float* __restrict__ att1,
                 const float* __restrict__ bias1, const float* __restrict__ prelu1,
                 float* __restrict__ out) {
    int gw = (blockIdx.x * blockDim.x + threadIdx.x) >> 5;
    if (gw >= NN) return;
    int n = gw;
    int lane = threadIdx.x & 31;
    int c0 = lane * 4, c1 = 128 + lane * 4;

    float4 weA = *(const float4*)(We1 + c0);
    float4 weB = *(const float4*)(We1 + c1);
    float4 atA = *(const float4*)(att1 + c0);
    float4 atB = *(const float4*)(att1 + c1);
    float4 xrA = *(const float4*)(d_xr1 + (size_t)n * EMBD + c0);
    float4 xrB = *(const float4*)(d_xr1 + (size_t)n * EMBD + c1);

    int rs = d_rowptr[n], re = d_rowptr[n + 1];
    float m = -1e30f, s = 0.f;
    float4 accA = make_float4(0.f, 0.f, 0.f, 0.f);
    float4 accB = make_float4(0.f, 0.f, 0.f, 0.f);

    for (int e = rs; e < re; e++) {
        int src = d_csrc[e];
        float w = d_cw[e];
        float4 xlA = *(const float4*)(d_xl1 + (size_t)src * EMBD + c0);
        float4 xlB = *(const float4*)(d_xl1 + (size_t)src * EMBD + c1);
        float part =
            lrelu(xlA.x + xrA.x + w * weA.x) * atA.x +
            lrelu(xlA.y + xrA.y + w * weA.y) * atA.y +
            lrelu(xlA.z + xrA.z + w * weA.z) * atA.z +
            lrelu(xlA.w + xrA.w + w * weA.w) * atA.w +
            lrelu(xlB.x + xrB.x + w * weB.x) * atB.x +
            lrelu(xlB.y + xrB.y + w * weB.y) * atB.y +
            lrelu(xlB.z + xrB.z + w * weB.z) * atB.z +
            lrelu(xlB.w + xrB.w + w * weB.w) * atB.w;
#pragma unroll
        for (int off = 16; off; off >>= 1)
            part += __shfl_xor_sync(0xffffffffu, part, off);
        float nm = fmaxf(m, part);
        float corr = __expf(m - nm);
        float p = __expf(part - nm);
        s = s * corr + p;
        accA.x = accA.x * corr + p * xlA.x;  accA.y = accA.y * corr + p * xlA.y;
        accA.z = accA.z * corr + p * xlA.z;  accA.w = accA.w * corr + p * xlA.w;
        accB.x = accB.x * corr + p * xlB.x;  accB.y = accB.y * corr + p * xlB.y;
        accB.z = accB.z * corr + p * xlB.z;  accB.w = accB.w * corr + p * xlB.w;
        m = nm;
    }
    float inv = 1.f / (s + 1e-16f);
    float4 bA = *(const float4*)(bias1 + c0);
    float4 bB = *(const float4*)(bias1 + c1);
    float4 pA = *(const float4*)(prelu1 + c0);
    float4 pB = *(const float4*)(prelu1 + c1);
    float4 skA = *(const float4*)(d_skp + (size_t)n * EMBD + c0);
    float4 skB = *(const float4*)(d_skp + (size_t)n * EMBD + c1);

    float o;
    float4 rA, rB;
    o = accA.x * inv + bA.x + skA.x; rA.x = o >= 0.f ? o : pA.x * o;
    o = accA.y * inv + bA.y + skA.y; rA.y = o >= 0.f ? o : pA.y * o;
    o = accA.z * inv + bA.z + skA.z; rA.z = o >= 0.f ? o : pA.z * o;
    o = accA.w * inv + bA.w + skA.w; rA.w = o >= 0.f ? o : pA.w * o;
    o = accB.x * inv + bB.x + skB.x; rB.x = o >= 0.f ? o : pB.x * o;
    o = accB.y * inv + bB.y + skB.y; rB.y = o >= 0.f ? o : pB.y * o;
    o = accB.z * inv + bB.z + skB.z; rB.z = o >= 0.f ? o : pB.z * o;
    o = accB.w * inv + bB.w + skB.w; rB.w = o >= 0.f ? o : pB.w * o;
    *(float4*)(out + (size_t)n * EMBD + c0) = rA;
    *(float4*)(out + (size_t)n * EMBD + c1) = rB;
}

// ---------------- launch -------------------------------------------------------
extern "C" void kernel_launch(void* const* d_in, const int* in_sizes, int n_in,
                              void* d_out, int out_size) {
    const float* x      = (const float*)d_in[0];
    const float* ew     = (const float*)d_in[1];
    const float* Wl0    = (const float*)d_in[2];
    const float* bl0    = (const float*)d_in[3];
    const float* Wr0    = (const float*)d_in[4];
    const float* br0    = (const float*)d_in[5];
    const float* We0    = (const float*)d_in[6];
    const float* att0   = (const float*)d_in[7];
    const float* bias0  = (const float*)d_in[8];
    const float* Wl1    = (const float*)d_in[9];
    const float* bl1    = (const float*)d_in[10];
    const float* Wr1    = (const float*)d_in[11];
    const float* br1    = (const float*)d_in[12];
    const float* We1    = (const float*)d_in[13];
    const float* att1   = (const float*)d_in[14];
    const float* bias1  = (const float*)d_in[15];
    const float* skipW  = (const float*)d_in[16];
    const float* skipb  = (const float*)d_in[17];
    const float* prelu0 = (const float*)d_in[18];
    const float* prelu1 = (const float*)d_in[19];
    const int*   eidx   = (const int*)d_in[20];
    float* out = (float*)d_out;

    float *xl0p, *xr0p, *h0p, *xl1p, *xr1p, *skpp;
    cudaGetSymbolAddress((void**)&xl0p, d_xl0);
    cudaGetSymbolAddress((void**)&xr0p, d_xr0);
    cudaGetSymbolAddress((void**)&h0p,  d_h0);
    cudaGetSymbolAddress((void**)&xl1p, d_xl1);
    cudaGetSymbolAddress((void**)&xr1p, d_xr1);
    cudaGetSymbolAddress((void**)&skpp, d_skp);

    // graph build
    zero_init_kernel<<<(NN + 255) / 256, 256>>>();
    hist_kernel<<<(EE + 255) / 256, 256>>>(eidx, ew);
    scan_kernel<<<1, 1024>>>();
    scatter_kernel<<<(ETOT + 255) / 256, 256>>>(eidx, ew);

    // layer 0 projections
    sgemm_bias<<<dim3(H0D / 128, (NN + 127) / 128), 256>>>(x, Wl0, bl0, xl0p, NN, IND, H0D);
    sgemm_bias<<<dim3(H0D / 128, (NN + 127) / 128), 256>>>(x, Wr0, br0, xr0p, NN, IND, H0D);

    // layer 0 attention + aggregate + bias + PReLU
    gat0_kernel<<<NN, 128>>>(We0, att0, bias0, prelu0);

    // layer 1 projections + skip
    sgemm_bias<<<dim3(EMBD / 128, (NN + 127) / 128), 256>>>(h0p, Wl1, bl1, xl1p, NN, H0D, EMBD);
    sgemm_bias<<<dim3(EMBD / 128, (NN + 127) / 128), 256>>>(h0p, Wr1, br1, xr1p, NN, H0D, EMBD);
    sgemm_bias<<<dim3(EMBD / 128, (NN + 127) / 128), 256>>>(x, skipW, skipb, skpp, NN, IND, EMBD);

    // layer 1 attention + aggregate + bias + skip + PReLU -> out
    gat1_kernel<<<(NN * 32 + 255) / 256, 256>>>(We1, att1, bias1, prelu1, out);

    (void)in_sizes; (void)n_in; (void)out_size;
}

// round 3
// speedup vs baseline: 1.5051x; 1.5051x over previous
#include <cuda_runtime.h>
#include <cstdint>

#define NN   10000
#define EE   160000
#define IND  256
#define H0D  512      // 4 heads * 128
#define EMBD 256
#define ETOT (EE + NN)

// ---------------- scratch (device globals; no allocations allowed) ------------
__device__ float d_wsum[NN];
__device__ int   d_cnt[NN];
__device__ int   d_rowptr[NN + 1];
__device__ int   d_fill[NN];
__device__ int   d_csrc[ETOT];
__device__ float d_cw[ETOT];
__device__ __align__(16) float d_xl0[(size_t)NN * H0D];
__device__ __align__(16) float d_xr0[(size_t)NN * H0D];
__device__ __align__(16) float d_h0 [(size_t)NN * H0D];
__device__ __align__(16) float d_xl1[(size_t)NN * EMBD];
__device__ __align__(16) float d_xr1[(size_t)NN * EMBD];
__device__ __align__(16) float d_skp[(size_t)NN * EMBD];

// ---------------- small utility kernels ---------------------------------------
__global__ void zero_init_kernel() {
    int i = blockIdx.x * blockDim.x + threadIdx.x;
    if (i < NN) { d_wsum[i] = 0.f; d_cnt[i] = 0; d_fill[i] = 0; }
}

__global__ void hist_kernel(const int* __restrict__ eidx, const float* __restrict__ ew) {
    int e = blockIdx.x * blockDim.x + threadIdx.x;
    if (e < EE) {
        int d = eidx[EE + e];            // dst row
        atomicAdd(&d_cnt[d], 1);
        atomicAdd(&d_wsum[d], ew[e]);
    }
}

// single-block exclusive scan over (cnt[i] + 1) -> d_rowptr
__global__ void scan_kernel() {
    __shared__ int sh[1024];
    const int CH = 10;                   // 1024*10 = 10240 >= NN
    int t = threadIdx.x;
    int base = t * CH;
    int loc[CH];
    int run = 0;
#pragma unroll
    for (int i = 0; i < CH; i++) {
        int idx = base + i;
        int c = (idx < NN) ? (d_cnt[idx] + 1) : 0;   // +1 self loop
        run += c;
        loc[i] = run;
    }
    sh[t] = run;
    __syncthreads();
    for (int off = 1; off < 1024; off <<= 1) {
        int v = (t >= off) ? sh[t - off] : 0;
        __syncthreads();
        sh[t] += v;
        __syncthreads();
    }
    int excl = sh[t] - run;
#pragma unroll
    for (int i = 0; i < CH; i++) {
        int idx = base + i;
        if (idx < NN) d_rowptr[idx + 1] = excl + loc[i];
    }
    if (t == 0) d_rowptr[0] = 0;
}

__global__ void scatter_kernel(const int* __restrict__ eidx, const float* __restrict__ ew) {
    int e = blockIdx.x * blockDim.x + threadIdx.x;
    if (e >= ETOT) return;
    int s, d; float w;
    if (e < EE) {
        s = eidx[e]; d = eidx[EE + e]; w = ew[e];
    } else {
        int n = e - EE;
        s = n; d = n;
        int c = d_cnt[n];
        w = (c > 0) ? (d_wsum[n] / (float)c) : 0.f;   // fill_value='mean'
    }
    int pos = d_rowptr[d] + atomicAdd(&d_fill[d], 1);
    d_csrc[pos] = s;
    d_cw[pos]   = w;
}

// ---------------- TF32 tensor-core GEMM (3xTF32 split, near-fp32 accuracy) -----
// C[M,N] = A[M,K] @ B[K,N] + bias[N]
// BM=128, BN=64, BK=16, 128 threads (4 warps, 2x2), warp tile 64x32.
// mma.sync m16n8k8 tf32: C += Ahi*Bhi + Alo*Bhi + Ahi*Blo.

__device__ __forceinline__ void tf32_split(float f, uint32_t& hi, uint32_t& lo) {
    uint32_t h;
    asm("cvt.rna.tf32.f32 %0, %1;" : "=r"(h) : "f"(f));
    float l = f - __uint_as_float(h);
    uint32_t lw;
    asm("cvt.rna.tf32.f32 %0, %1;" : "=r"(lw) : "f"(l));
    hi = h; lo = lw;
}

__device__ __forceinline__ void mma8(float* c, const uint32_t* a, const uint32_t* b) {
    asm volatile(
        "mma.sync.aligned.m16n8k8.row.col.f32.tf32.tf32.f32 "
        "{%0,%1,%2,%3}, {%4,%5,%6,%7}, {%8,%9}, {%0,%1,%2,%3};"
        : "+f"(c[0]), "+f"(c[1]), "+f"(c[2]), "+f"(c[3])
        : "r"(a[0]), "r"(a[1]), "r"(a[2]), "r"(a[3]), "r"(b[0]), "r"(b[1]));
}

#define ASTR 132
#define BSTR 68

__global__ __launch_bounds__(128)
void gemm_tf32_bias(const float* __restrict__ A, const float* __restrict__ B,
                    const float* __restrict__ bias, float* __restrict__ C,
                    int M, int K, int N) {
    __shared__ float As[2][16][ASTR];
    __shared__ float Bs[2][16][BSTR];

    const int tid  = threadIdx.x;
    const int warp = tid >> 5;
    const int lane = tid & 31;
    const int r = lane >> 2;       // 0..7
    const int q = lane & 3;        // 0..3

    const int warp_m = (warp & 1) * 64;
    const int warp_n = (warp >> 1) * 32;
    const int m0 = blockIdx.y * 128;
    const int n0 = blockIdx.x * 64;

    float acc[4][4][4];
#pragma unroll
    for (int i = 0; i < 4; i++)
#pragma unroll
        for (int j = 0; j < 4; j++)
#pragma unroll
            for (int k = 0; k < 4; k++) acc[i][j][k] = 0.f;

    // global staging regs
    float4 ar[4];
    float4 br[2];
    const int am = m0 + tid;                 // A row this thread stages
    const bool avalid = (am < M);
    const int bkr = tid >> 3;                // 0..15  B k-row
    const int bnc = (tid & 7) * 8;           // 0..56  B col offset

    const int nstages = K >> 4;

    // prologue load stage 0
    {
        const float* ap = A + (size_t)am * K;
#pragma unroll
        for (int i = 0; i < 4; i++)
            ar[i] = avalid ? *(const float4*)(ap + i * 4)
                           : make_float4(0.f, 0.f, 0.f, 0.f);
        const float* bp = B + (size_t)bkr * N + n0 + bnc;
        br[0] = *(const float4*)(bp);
        br[1] = *(const float4*)(bp + 4);
    }
    // store stage 0
    {
#pragma unroll
        for (int i = 0; i < 4; i++) {
            As[0][i * 4 + 0][tid] = ar[i].x;
            As[0][i * 4 + 1][tid] = ar[i].y;
            As[0][i * 4 + 2][tid] = ar[i].z;
            As[0][i * 4 + 3][tid] = ar[i].w;
        }
        *(float4*)&Bs[0][bkr][bnc]     = br[0];
        *(float4*)&Bs[0][bkr][bnc + 4] = br[1];
    }
    __syncthreads();

    for (int s = 0; s < nstages; s++) {
        const int buf = s & 1;
        // prefetch next stage into regs
        if (s + 1 < nstages) {
            const int k0 = (s + 1) << 4;
            const float* ap = A + (size_t)am * K + k0;
#pragma unroll
            for (int i = 0; i < 4; i++)
                ar[i] = avalid ? *(const float4*)(ap + i * 4)
                               : make_float4(0.f, 0.f, 0.f, 0.f);
            const float* bp = B + (size_t)(k0 + bkr) * N + n0 + bnc;
            br[0] = *(const float4*)(bp);
            br[1] = *(const float4*)(bp + 4);
        }

        // compute 2 k-steps of 8
#pragma unroll
        for (int ks = 0; ks < 16; ks += 8) {
            uint32_t ahi[4][4], alo[4][4];
#pragma unroll
            for (int mt = 0; mt < 4; mt++) {
                const int mm = warp_m + mt * 16;
                float f0 = As[buf][ks + q][mm + r];
                float f1 = As[buf][ks + q][mm + r + 8];
                float f2 = As[buf][ks + q + 4][mm + r];
                float f3 = As[buf][ks + q + 4][mm + r + 8];
                tf32_split(f0, ahi[mt][0], alo[mt][0]);
                tf32_split(f1, ahi[mt][1], alo[mt][1]);
                tf32_split(f2, ahi[mt][2], alo[mt][2]);
                tf32_split(f3, ahi[mt][3], alo[mt][3]);
            }
            uint32_t bhi[4][2], blo[4][2];
#pragma unroll
            for (int nt = 0; nt < 4; nt++) {
                const int nn = warp_n + nt * 8;
                float g0 = Bs[buf][ks + q][nn + r];
                float g1 = Bs[buf][ks + q + 4][nn + r];
                tf32_split(g0, bhi[nt][0], blo[nt][0]);
                tf32_split(g1, bhi[nt][1], blo[nt][1]);
            }
#pragma unroll
            for (int mt = 0; mt < 4; mt++)
#pragma unroll
                for (int nt = 0; nt < 4; nt++) {
                    mma8(acc[mt][nt], ahi[mt], bhi[nt]);
                    mma8(acc[mt][nt], alo[mt], bhi[nt]);
                    mma8(acc[mt][nt], ahi[mt], blo[nt]);
                }
        }

        // store prefetched stage
        if (s + 1 < nstages) {
            const int nb = (s + 1) & 1;
#pragma unroll
            for (int i = 0; i < 4; i++) {
                As[nb][i * 4 + 0][tid] = ar[i].x;
                As[nb][i * 4 + 1][tid] = ar[i].y;
                As[nb][i * 4 + 2][tid] = ar[i].z;
                As[nb][i * 4 + 3][tid] = ar[i].w;
            }
            *(float4*)&Bs[nb][bkr][bnc]     = br[0];
            *(float4*)&Bs[nb][bkr][bnc + 4] = br[1];
        }
        __syncthreads();
    }

    // epilogue: C[m][n] = acc + bias[n]
#pragma unroll
    for (int mt = 0; mt < 4; mt++) {
#pragma unroll
        for (int nt = 0; nt < 4; nt++) {
            const int col = n0 + warp_n + nt * 8 + 2 * q;
            const float bx = bias[col];
            const float by = bias[col + 1];
            const int row0 = m0 + warp_m + mt * 16 + r;
            const int row1 = row0 + 8;
            if (row0 < M) {
                float2 v = make_float2(acc[mt][nt][0] + bx, acc[mt][nt][1] + by);
                *(float2*)(C + (size_t)row0 * N + col) = v;
            }
            if (row1 < M) {
                float2 v = make_float2(acc[mt][nt][2] + bx, acc[mt][nt][3] + by);
                *(float2*)(C + (size_t)row1 * N + col) = v;
            }
        }
    }
}

// ---------------- GAT layer 0: 4 heads x 128, block per node -------------------
__device__ __forceinline__ float lrelu(float v) { return v >= 0.f ? v : 0.2f * v; }

__global__ __launch_bounds__(128)
void gat0_kernel(const float* __restrict__ We0, const float* __restrict__ att0,
                 const float* __restrict__ bias0, const float* __restrict__ prelu0) {
    int n = blockIdx.x;
    int lane = threadIdx.x & 31;
    int h = threadIdx.x >> 5;
    int c = h * 128 + lane * 4;

    float4 we = *(const float4*)(We0 + c);
    float4 at = *(const float4*)(att0 + c);          // att0[h,:] linear = h*128+c
    float4 xr = *(const float4*)(d_xr0 + (size_t)n * H0D + c);

    int rs = d_rowptr[n], re = d_rowptr[n + 1];
    float m = -1e30f, s = 0.f;
    float4 acc = make_float4(0.f, 0.f, 0.f, 0.f);

    for (int e = rs; e < re; e++) {
        int src = d_csrc[e];
        float w = d_cw[e];
        float4 xl = *(const float4*)(d_xl0 + (size_t)src * H0D + c);
        float vx = lrelu(xl.x + xr.x + w * we.x);
        float vy = lrelu(xl.y + xr.y + w * we.y);
        float vz = lrelu(xl.z + xr.z + w * we.z);
        float vw = lrelu(xl.w + xr.w + w * we.w);
        float part = vx * at.x + vy * at.y + vz * at.z + vw * at.w;
#pragma unroll
        for (int off = 16; off; off >>= 1)
            part += __shfl_xor_sync(0xffffffffu, part, off);
        float nm = fmaxf(m, part);
        float corr = __expf(m - nm);
        float p = __expf(part - nm);
        s = s * corr + p;
        acc.x = acc.x * corr + p * xl.x;
        acc.y = acc.y * corr + p * xl.y;
        acc.z = acc.z * corr + p * xl.z;
        acc.w = acc.w * corr + p * xl.w;
        m = nm;
    }
    float inv = 1.f / (s + 1e-16f);
    float4 b = *(const float4*)(bias0 + c);
    float4 pr = *(const float4*)(prelu0 + c);
    float ox = acc.x * inv + b.x; ox = ox >= 0.f ? ox : pr.x * ox;
    float oy = acc.y * inv + b.y; oy = oy >= 0.f ? oy : pr.y * oy;
    float oz = acc.z * inv + b.z; oz = oz >= 0.f ? oz : pr.z * oz;
    float ow = acc.w * inv + b.w; ow = ow >= 0.f ? ow : pr.w * ow;
    *(float4*)(d_h0 + (size_t)n * H0D + c) = make_float4(ox, oy, oz, ow);
}

// ---------------- GAT layer 1: 1 head x 256, warp per node ---------------------
__global__ __launch_bounds__(256)
void gat1_kernel(const float* __restrict__ We1, const float* __restrict__ att1,
                 const float* __restrict__ bias1, const float* __restrict__ prelu1,
                 float* __restrict__ out) {
    int gw = (blockIdx.x * blockDim.x + threadIdx.x) >> 5;
    if (gw >= NN) return;
    int n = gw;
    int lane = threadIdx.x & 31;
    int c0 = lane * 4, c1 = 128 + lane * 4;

    float4 weA = *(const float4*)(We1 + c0);
    float4 weB = *(const float4*)(We1 + c1);
    float4 atA = *(const float4*)(att1 + c0);
    float4 atB = *(const float4*)(att1 + c1);
    float4 xrA = *(const float4*)(d_xr1 + (size_t)n * EMBD + c0);
    float4 xrB = *(const float4*)(d_xr1 + (size_t)n * EMBD + c1);

    int rs = d_rowptr[n], re = d_rowptr[n + 1];
    float m = -1e30f, s = 0.f;
    float4 accA = make_float4(0.f, 0.f, 0.f, 0.f);
    float4 accB = make_float4(0.f, 0.f, 0.f, 0.f);

    for (int e = rs; e < re; e++) {
        int src = d_csrc[e];
        float w = d_cw[e];
        float4 xlA = *(const float4*)(d_xl1 + (size_t)src * EMBD + c0);
        float4 xlB = *(const float4*)(d_xl1 + (size_t)src * EMBD + c1);
        float part =
            lrelu(xlA.x + xrA.x + w * weA.x) * atA.x +
            lrelu(xlA.y + xrA.y + w * weA.y) * atA.y +
            lrelu(xlA.z + xrA.z + w * weA.z) * atA.z +
            lrelu(xlA.w + xrA.w + w * weA.w) * atA.w +
            lrelu(xlB.x + xrB.x + w * weB.x) * atB.x +
            lrelu(xlB.y + xrB.y + w * weB.y) * atB.y +
            lrelu(xlB.z + xrB.z + w * weB.z) * atB.z +
            lrelu(xlB.w + xrB.w + w * weB.w) * atB.w;
#pragma unroll
        for (int off = 16; off; off >>= 1)
            part += __shfl_xor_sync(0xffffffffu, part, off);
        float nm = fmaxf(m, part);
        float corr = __expf(m - nm);
        float p = __expf(part - nm);
        s = s * corr + p;
        accA.x = accA.x * corr + p * xlA.x;  accA.y = accA.y * corr + p * xlA.y;
        accA.z = accA.z * corr + p * xlA.z;  accA.w = accA.w * corr + p * xlA.w;
        accB.x = accB.x * corr + p * xlB.x;  accB.y = accB.y * corr + p * xlB.y;
        accB.z = accB.z * corr + p * xlB.z;  accB.w = accB.w * corr + p * xlB.w;
        m = nm;
    }
    float inv = 1.f / (s + 1e-16f);
    float4 bA = *(const float4*)(bias1 + c0);
    float4 bB = *(const float4*)(bias1 + c1);
    float4 pA = *(const float4*)(prelu1 + c0);
    float4 pB = *(const float4*)(prelu1 + c1);
    float4 skA = *(const float4*)(d_skp + (size_t)n * EMBD + c0);
    float4 skB = *(const float4*)(d_skp + (size_t)n * EMBD + c1);

    float o;
    float4 rA, rB;
    o = accA.x * inv + bA.x + skA.x; rA.x = o >= 0.f ? o : pA.x * o;
    o = accA.y * inv + bA.y + skA.y; rA.y = o >= 0.f ? o : pA.y * o;
    o = accA.z * inv + bA.z + skA.z; rA.z = o >= 0.f ? o : pA.z * o;
    o = accA.w * inv + bA.w + skA.w; rA.w = o >= 0.f ? o : pA.w * o;
    o = accB.x * inv + bB.x + skB.x; rB.x = o >= 0.f ? o : pB.x * o;
    o = accB.y * inv + bB.y + skB.y; rB.y = o >= 0.f ? o : pB.y * o;
    o = accB.z * inv + bB.z + skB.z; rB.z = o >= 0.f ? o : pB.z * o;
    o = accB.w * inv + bB.w + skB.w; rB.w = o >= 0.f ? o : pB.w * o;
    *(float4*)(out + (size_t)n * EMBD + c0) = rA;
    *(float4*)(out + (size_t)n * EMBD + c1) = rB;
}

// ---------------- launch -------------------------------------------------------
extern "C" void kernel_launch(void* const* d_in, const int* in_sizes, int n_in,
                              void* d_out, int out_size) {
    const float* x      = (const float*)d_in[0];
    const float* ew     = (const float*)d_in[1];
    const float* Wl0    = (const float*)d_in[2];
    const float* bl0    = (const float*)d_in[3];
    const float* Wr0    = (const float*)d_in[4];
    const float* br0    = (const float*)d_in[5];
    const float* We0    = (const float*)d_in[6];
    const float* att0   = (const float*)d_in[7];
    const float* bias0  = (const float*)d_in[8];
    const float* Wl1    = (const float*)d_in[9];
    const float* bl1    = (const float*)d_in[10];
    const float* Wr1    = (const float*)d_in[11];
    const float* br1    = (const float*)d_in[12];
    const float* We1    = (const float*)d_in[13];
    const float* att1   = (const float*)d_in[14];
    const float* bias1  = (const float*)d_in[15];
    const float* skipW  = (const float*)d_in[16];
    const float* skipb  = (const float*)d_in[17];
    const float* prelu0 = (const float*)d_in[18];
    const float* prelu1 = (const float*)d_in[19];
    const int*   eidx   = (const int*)d_in[20];
    float* out = (float*)d_out;

    float *xl0p, *xr0p, *h0p, *xl1p, *xr1p, *skpp;
    cudaGetSymbolAddress((void**)&xl0p, d_xl0);
    cudaGetSymbolAddress((void**)&xr0p, d_xr0);
    cudaGetSymbolAddress((void**)&h0p,  d_h0);
    cudaGetSymbolAddress((void**)&xl1p, d_xl1);
    cudaGetSymbolAddress((void**)&xr1p, d_xr1);
    cudaGetSymbolAddress((void**)&skpp, d_skp);

    const int MB = (NN + 127) / 128;

    // graph build
    zero_init_kernel<<<(NN + 255) / 256, 256>>>();
    hist_kernel<<<(EE + 255) / 256, 256>>>(eidx, ew);
    scan_kernel<<<1, 1024>>>();
    scatter_kernel<<<(ETOT + 255) / 256, 256>>>(eidx, ew);

    // layer 0 projections (tensor cores, 3xTF32)
    gemm_tf32_bias<<<dim3(H0D / 64, MB), 128>>>(x, Wl0, bl0, xl0p, NN, IND, H0D);
    gemm_tf32_bias<<<dim3(H0D / 64, MB), 128>>>(x, Wr0, br0, xr0p, NN, IND, H0D);

    // layer 0 attention + aggregate + bias + PReLU
    gat0_kernel<<<NN, 128>>>(We0, att0, bias0, prelu0);

    // layer 1 projections + skip (tensor cores, 3xTF32)
    gemm_tf32_bias<<<dim3(EMBD / 64, MB), 128>>>(h0p, Wl1, bl1, xl1p, NN, H0D, EMBD);
    gemm_tf32_bias<<<dim3(EMBD / 64, MB), 128>>>(h0p, Wr1, br1, xr1p, NN, H0D, EMBD);
    gemm_tf32_bias<<<dim3(EMBD / 64, MB), 128>>>(x, skipW, skipb, skpp, NN, IND, EMBD);

    // layer 1 attention + aggregate + bias + skip + PReLU -> out
    gat1_kernel<<<(NN * 32 + 255) / 256, 256>>>(We1, att1, bias1, prelu1, out);

    (void)in_sizes; (void)n_in; (void)out_size;
}

// round 4
// speedup vs baseline: 1.7773x; 1.1809x over previous
#include <cuda_runtime.h>
#include <cstdint>

#define NN   10000
#define EE   160000
#define IND  256
#define H0D  512      // 4 heads * 128
#define EMBD 256
#define ETOT (EE + NN)

// ---------------- scratch (device globals; no allocations allowed) ------------
__device__ float d_wsum[NN];
__device__ int   d_cnt[NN];
__device__ int   d_rowptr[NN + 1];
__device__ int   d_fill[NN];
__device__ int   d_csrc[ETOT];
__device__ float d_cw[ETOT];
__device__ __align__(16) float d_xl0[(size_t)NN * H0D];
__device__ __align__(16) float d_xr0[(size_t)NN * H0D];
__device__ __align__(16) float d_xl1[(size_t)NN * EMBD];
__device__ __align__(16) float d_xr1[(size_t)NN * EMBD];
__device__ __align__(16) float d_skp[(size_t)NN * EMBD];

// packed bf16x2 hi/lo operands
__device__ __align__(16) uint32_t d_xh [(size_t)NN * IND / 2];
__device__ __align__(16) uint32_t d_xlo[(size_t)NN * IND / 2];
__device__ __align__(16) uint32_t d_h0h[(size_t)NN * H0D / 2];
__device__ __align__(16) uint32_t d_h0l[(size_t)NN * H0D / 2];
__device__ __align__(16) uint32_t d_Wl0h[IND * H0D / 2], d_Wl0l[IND * H0D / 2];
__device__ __align__(16) uint32_t d_Wr0h[IND * H0D / 2], d_Wr0l[IND * H0D / 2];
__device__ __align__(16) uint32_t d_Wl1h[H0D * EMBD / 2], d_Wl1l[H0D * EMBD / 2];
__device__ __align__(16) uint32_t d_Wr1h[H0D * EMBD / 2], d_Wr1l[H0D * EMBD / 2];
__device__ __align__(16) uint32_t d_Wsh [IND * EMBD / 2], d_Wsl [IND * EMBD / 2];

// ---------------- bf16 split helpers -------------------------------------------
__device__ __forceinline__ uint32_t pack_bf2(float even_, float odd_) {
    uint32_t w;
    asm("cvt.rn.bf16x2.f32 %0, %1, %2;" : "=r"(w) : "f"(odd_), "f"(even_));
    return w;
}
__device__ __forceinline__ float bf_lo(uint32_t w) { return __uint_as_float(w << 16); }
__device__ __forceinline__ float bf_hi(uint32_t w) { return __uint_as_float(w & 0xffff0000u); }

__device__ __forceinline__ void split2(float f0, float f1, uint32_t& hi, uint32_t& lo) {
    hi = pack_bf2(f0, f1);
    lo = pack_bf2(f0 - bf_lo(hi), f1 - bf_hi(hi));
}

// A-format: row-major [M][K] -> packed words [M][K/2] (consecutive-k pairs)
__global__ void split_rows_kernel(const float* __restrict__ A,
                                  uint32_t* __restrict__ Hh, uint32_t* __restrict__ Hl,
                                  int nwords) {
    int i = blockIdx.x * blockDim.x + threadIdx.x;
    if (i >= nwords) return;
    float2 f = ((const float2*)A)[i];
    uint32_t hi, lo;
    split2(f.x, f.y, hi, lo);
    Hh[i] = hi; Hl[i] = lo;
}

// B-format: [K][N] -> k-pair interleaved words [K/2][N]: word(k2,n) = {B[2k2][n], B[2k2+1][n]}
__global__ void split_B_kernel(const float* __restrict__ B,
                               uint32_t* __restrict__ Bh, uint32_t* __restrict__ Bl,
                               int K, int N) {
    int i = blockIdx.x * blockDim.x + threadIdx.x;
    int total = (K >> 1) * N;
    if (i >= total) return;
    int k2 = i / N, n = i - k2 * N;
    float f0 = B[(size_t)(2 * k2) * N + n];
    float f1 = B[(size_t)(2 * k2 + 1) * N + n];
    uint32_t hi, lo;
    split2(f0, f1, hi, lo);
    Bh[i] = hi; Bl[i] = lo;
}

// ---------------- small utility kernels ---------------------------------------
__global__ void zero_init_kernel() {
    int i = blockIdx.x * blockDim.x + threadIdx.x;
    if (i < NN) { d_wsum[i] = 0.f; d_cnt[i] = 0; d_fill[i] = 0; }
}

__global__ void hist_kernel(const int* __restrict__ eidx, const float* __restrict__ ew) {
    int e = blockIdx.x * blockDim.x + threadIdx.x;
    if (e < EE) {
        int d = eidx[EE + e];            // dst row
        atomicAdd(&d_cnt[d], 1);
        atomicAdd(&d_wsum[d], ew[e]);
    }
}

// single-block exclusive scan over (cnt[i] + 1) -> d_rowptr
__global__ void scan_kernel() {
    __shared__ int sh[1024];
    const int CH = 10;
    int t = threadIdx.x;
    int base = t * CH;
    int loc[CH];
    int run = 0;
#pragma unroll
    for (int i = 0; i < CH; i++) {
        int idx = base + i;
        int c = (idx < NN) ? (d_cnt[idx] + 1) : 0;
        run += c;
        loc[i] = run;
    }
    sh[t] = run;
    __syncthreads();
    for (int off = 1; off < 1024; off <<= 1) {
        int v = (t >= off) ? sh[t - off] : 0;
        __syncthreads();
        sh[t] += v;
        __syncthreads();
    }
    int excl = sh[t] - run;
#pragma unroll
    for (int i = 0; i < CH; i++) {
        int idx = base + i;
        if (idx < NN) d_rowptr[idx + 1] = excl + loc[i];
    }
    if (t == 0) d_rowptr[0] = 0;
}

__global__ void scatter_kernel(const int* __restrict__ eidx, const float* __restrict__ ew) {
    int e = blockIdx.x * blockDim.x + threadIdx.x;
    if (e >= ETOT) return;
    int s, d; float w;
    if (e < EE) {
        s = eidx[e]; d = eidx[EE + e]; w = ew[e];
    } else {
        int n = e - EE;
        s = n; d = n;
        int c = d_cnt[n];
        w = (c > 0) ? (d_wsum[n] / (float)c) : 0.f;
    }
    int pos = d_rowptr[d] + atomicAdd(&d_fill[d], 1);
    d_csrc[pos] = s;
    d_cw[pos]   = w;
}

// ---------------- bf16x3 tensor-core GEMM --------------------------------------
// C[M,N] = A[M,K] @ B[K,N] + bias[N], error-compensated bf16 (hi*hi + lo*hi + hi*lo).
// BM=128, BN=64, BK=16, 128 threads (4 warps 2x2), warp tile 64x32.
// Operands pre-split: A packed words [M][K/2], B packed words [K/2][N].

__device__ __forceinline__ void mma16(float* c, const uint32_t* a, const uint32_t* b) {
    asm volatile(
        "mma.sync.aligned.m16n8k16.row.col.f32.bf16.bf16.f32 "
        "{%0,%1,%2,%3}, {%4,%5,%6,%7}, {%8,%9}, {%0,%1,%2,%3};"
        : "+f"(c[0]), "+f"(c[1]), "+f"(c[2]), "+f"(c[3])
        : "r"(a[0]), "r"(a[1]), "r"(a[2]), "r"(a[3]), "r"(b[0]), "r"(b[1]));
}

#define ASTR2 136
#define BSTR2 72

__global__ __launch_bounds__(128)
void gemm_bf16x3(const uint32_t* __restrict__ Ah, const uint32_t* __restrict__ Al,
                 const uint32_t* __restrict__ Bh, const uint32_t* __restrict__ Bl,
                 const float* __restrict__ bias, float* __restrict__ C,
                 int M, int K, int N) {
    __shared__ uint32_t Ahs[2][8][ASTR2];
    __shared__ uint32_t Als[2][8][ASTR2];
    __shared__ uint32_t Bhs[2][8][BSTR2];
    __shared__ uint32_t Bls[2][8][BSTR2];

    const int tid  = threadIdx.x;
    const int warp = tid >> 5;
    const int lane = tid & 31;
    const int r = lane >> 2;       // 0..7
    const int q = lane & 3;        // 0..3

    const int warp_m = (warp & 1) * 64;
    const int warp_n = (warp >> 1) * 32;
    const int m0 = blockIdx.y * 128;
    const int n0 = blockIdx.x * 64;
    const int Kw = K >> 1;         // words per A row

    float acc[4][4][4];
#pragma unroll
    for (int i = 0; i < 4; i++)
#pragma unroll
        for (int j = 0; j < 4; j++)
#pragma unroll
            for (int k = 0; k < 4; k++) acc[i][j][k] = 0.f;

    const int am = m0 + tid;
    const bool avalid = (am < M);
    const int brow = tid >> 4;            // 0..7 (k2 within stage)
    const int bcolw = (tid & 15) * 4;     // 0..60 word col

    const int nstages = K >> 4;
    const uint4 z4 = make_uint4(0u, 0u, 0u, 0u);

    uint4 ahA, ahB, alA, alB, bh4, bl4;

    // prologue: load stage 0
    {
        const uint32_t* ap = Ah + (size_t)am * Kw;
        const uint32_t* alp = Al + (size_t)am * Kw;
        ahA = avalid ? *(const uint4*)(ap) : z4;
        ahB = avalid ? *(const uint4*)(ap + 4) : z4;
        alA = avalid ? *(const uint4*)(alp) : z4;
        alB = avalid ? *(const uint4*)(alp + 4) : z4;
        const uint32_t* bp = Bh + (size_t)brow * N + n0 + bcolw;
        const uint32_t* blp = Bl + (size_t)brow * N + n0 + bcolw;
        bh4 = *(const uint4*)bp;
        bl4 = *(const uint4*)blp;
    }
    {
        Ahs[0][0][tid] = ahA.x; Ahs[0][1][tid] = ahA.y; Ahs[0][2][tid] = ahA.z; Ahs[0][3][tid] = ahA.w;
        Ahs[0][4][tid] = ahB.x; Ahs[0][5][tid] = ahB.y; Ahs[0][6][tid] = ahB.z; Ahs[0][7][tid] = ahB.w;
        Als[0][0][tid] = alA.x; Als[0][1][tid] = alA.y; Als[0][2][tid] = alA.z; Als[0][3][tid] = alA.w;
        Als[0][4][tid] = alB.x; Als[0][5][tid] = alB.y; Als[0][6][tid] = alB.z; Als[0][7][tid] = alB.w;
        *(uint4*)&Bhs[0][brow][bcolw] = bh4;
        *(uint4*)&Bls[0][brow][bcolw] = bl4;
    }
    __syncthreads();

    for (int s = 0; s < nstages; s++) {
        const int buf = s & 1;
        if (s + 1 < nstages) {
            const int w0 = (s + 1) * 8;
            const uint32_t* ap  = Ah + (size_t)am * Kw + w0;
            const uint32_t* alp = Al + (size_t)am * Kw + w0;
            ahA = avalid ? *(const uint4*)(ap) : z4;
            ahB = avalid ? *(const uint4*)(ap + 4) : z4;
            alA = avalid ? *(const uint4*)(alp) : z4;
            alB = avalid ? *(const uint4*)(alp + 4) : z4;
            const uint32_t* bp  = Bh + (size_t)(w0 + brow) * N + n0 + bcolw;
            const uint32_t* blp = Bl + (size_t)(w0 + brow) * N + n0 + bcolw;
            bh4 = *(const uint4*)bp;
            bl4 = *(const uint4*)blp;
        }

        // fragments for this k16
        uint32_t ah[4][4], al[4][4];
#pragma unroll
        for (int mt = 0; mt < 4; mt++) {
            const int mm = warp_m + mt * 16;
            ah[mt][0] = Ahs[buf][q][mm + r];
            ah[mt][1] = Ahs[buf][q][mm + r + 8];
            ah[mt][2] = Ahs[buf][q + 4][mm + r];
            ah[mt][3] = Ahs[buf][q + 4][mm + r + 8];
            al[mt][0] = Als[buf][q][mm + r];
            al[mt][1] = Als[buf][q][mm + r + 8];
            al[mt][2] = Als[buf][q + 4][mm + r];
            al[mt][3] = Als[buf][q + 4][mm + r + 8];
        }
        uint32_t bh[4][2], bl[4][2];
#pragma unroll
        for (int nt = 0; nt < 4; nt++) {
            const int nn = warp_n + nt * 8;
            bh[nt][0] = Bhs[buf][q][nn + r];
            bh[nt][1] = Bhs[buf][q + 4][nn + r];
            bl[nt][0] = Bls[buf][q][nn + r];
            bl[nt][1] = Bls[buf][q + 4][nn + r];
        }
#pragma unroll
        for (int mt = 0; mt < 4; mt++)
#pragma unroll
            for (int nt = 0; nt < 4; nt++) {
                mma16(acc[mt][nt], ah[mt], bh[nt]);
                mma16(acc[mt][nt], al[mt], bh[nt]);
                mma16(acc[mt][nt], ah[mt], bl[nt]);
            }

        if (s + 1 < nstages) {
            const int nb = (s + 1) & 1;
            Ahs[nb][0][tid] = ahA.x; Ahs[nb][1][tid] = ahA.y; Ahs[nb][2][tid] = ahA.z; Ahs[nb][3][tid] = ahA.w;
            Ahs[nb][4][tid] = ahB.x; Ahs[nb][5][tid] = ahB.y; Ahs[nb][6][tid] = ahB.z; Ahs[nb][7][tid] = ahB.w;
            Als[nb][0][tid] = alA.x; Als[nb][1][tid] = alA.y; Als[nb][2][tid] = alA.z; Als[nb][3][tid] = alA.w;
            Als[nb][4][tid] = alB.x; Als[nb][5][tid] = alB.y; Als[nb][6][tid] = alB.z; Als[nb][7][tid] = alB.w;
            *(uint4*)&Bhs[nb][brow][bcolw] = bh4;
            *(uint4*)&Bls[nb][brow][bcolw] = bl4;
        }
        __syncthreads();
    }

    // epilogue
#pragma unroll
    for (int mt = 0; mt < 4; mt++) {
#pragma unroll
        for (int nt = 0; nt < 4; nt++) {
            const int col = n0 + warp_n + nt * 8 + 2 * q;
            const float bx = bias[col];
            const float by = bias[col + 1];
            const int row0 = m0 + warp_m + mt * 16 + r;
            const int row1 = row0 + 8;
            if (row0 < M) {
                float2 v = make_float2(acc[mt][nt][0] + bx, acc[mt][nt][1] + by);
                *(float2*)(C + (size_t)row0 * N + col) = v;
            }
            if (row1 < M) {
                float2 v = make_float2(acc[mt][nt][2] + bx, acc[mt][nt][3] + by);
                *(float2*)(C + (size_t)row1 * N + col) = v;
            }
        }
    }
}

// ---------------- GAT layer 0: 4 heads x 128, block per node -------------------
__device__ __forceinline__ float lrelu(float v) { return v >= 0.f ? v : 0.2f * v; }

__global__ __launch_bounds__(128)
void gat0_kernel(const float* __restrict__ We0, const float* __restrict__ att0,
                 const float* __restrict__ bias0, const float* __restrict__ prelu0) {
    int n = blockIdx.x;
    int lane = threadIdx.x & 31;
    int h = threadIdx.x >> 5;
    int c = h * 128 + lane * 4;

    float4 we = *(const float4*)(We0 + c);
    float4 at = *(const float4*)(att0 + c);
    float4 xr = *(const float4*)(d_xr0 + (size_t)n * H0D + c);

    int rs = d_rowptr[n], re = d_rowptr[n + 1];
    float m = -1e30f, s = 0.f;
    float4 acc = make_float4(0.f, 0.f, 0.f, 0.f);

    for (int e = rs; e < re; e++) {
        int src = d_csrc[e];
        float w = d_cw[e];
        float4 xl = *(const float4*)(d_xl0 + (size_t)src * H0D + c);
        float vx = lrelu(xl.x + xr.x + w * we.x);
        float vy = lrelu(xl.y + xr.y + w * we.y);
        float vz = lrelu(xl.z + xr.z + w * we.z);
        float vw = lrelu(xl.w + xr.w + w * we.w);
        float part = vx * at.x + vy * at.y + vz * at.z + vw * at.w;
#pragma unroll
        for (int off = 16; off; off >>= 1)
            part += __shfl_xor_sync(0xffffffffu, part, off);
        float nm = fmaxf(m, part);
        float corr = __expf(m - nm);
        float p = __expf(part - nm);
        s = s * corr + p;
        acc.x = acc.x * corr + p * xl.x;
        acc.y = acc.y * corr + p * xl.y;
        acc.z = acc.z * corr + p * xl.z;
        acc.w = acc.w * corr + p * xl.w;
        m = nm;
    }
    float inv = 1.f / (s + 1e-16f);
    float4 b = *(const float4*)(bias0 + c);
    float4 pr = *(const float4*)(prelu0 + c);
    float ox = acc.x * inv + b.x; ox = ox >= 0.f ? ox : pr.x * ox;
    float oy = acc.y * inv + b.y; oy = oy >= 0.f ? oy : pr.y * oy;
    float oz = acc.z * inv + b.z; oz = oz >= 0.f ? oz : pr.z * oz;
    float ow = acc.w * inv + b.w; ow = ow >= 0.f ? ow : pr.w * ow;

    // write h0 directly in split bf16 hi/lo packed form (layer-1 A operand)
    uint32_t w0h, w0l, w1h, w1l;
    split2(ox, oy, w0h, w0l);
    split2(oz, ow, w1h, w1l);
    size_t widx = ((size_t)n * H0D + c) >> 1;
    *(uint2*)(d_h0h + widx) = make_uint2(w0h, w1h);
    *(uint2*)(d_h0l + widx) = make_uint2(w0l, w1l);
}

// ---------------- GAT layer 1: 1 head x 256, warp per node ---------------------
__global__ __launch_bounds__(256)
void gat1_kernel(const float* __restrict__ We1, const float* __restrict__ att1,
                 const float* __restrict__ bias1, const float* __restrict__ prelu1,
                 float* __restrict__ out) {
    int gw = (blockIdx.x * blockDim.x + threadIdx.x) >> 5;
    if (gw >= NN) return;
    int n = gw;
    int lane = threadIdx.x & 31;
    int c0 = lane * 4, c1 = 128 + lane * 4;

    float4 weA = *(const float4*)(We1 + c0);
    float4 weB = *(const float4*)(We1 + c1);
    float4 atA = *(const float4*)(att1 + c0);
    float4 atB = *(const float4*)(att1 + c1);
    float4 xrA = *(const float4*)(d_xr1 + (size_t)n * EMBD + c0);
    float4 xrB = *(const float4*)(d_xr1 + (size_t)n * EMBD + c1);

    int rs = d_rowptr[n], re = d_rowptr[n + 1];
    float m = -1e30f, s = 0.f;
    float4 accA = make_float4(0.f, 0.f, 0.f, 0.f);
    float4 accB = make_float4(0.f, 0.f, 0.f, 0.f);

    for (int e = rs; e < re; e++) {
        int src = d_csrc[e];
        float w = d_cw[e];
        float4 xlA = *(const float4*)(d_xl1 + (size_t)src * EMBD + c0);
        float4 xlB = *(const float4*)(d_xl1 + (size_t)src * EMBD + c1);
        float part =
            lrelu(xlA.x + xrA.x + w * weA.x) * atA.x +
            lrelu(xlA.y + xrA.y + w * weA.y) * atA.y +
            lrelu(xlA.z + xrA.z + w * weA.z) * atA.z +
            lrelu(xlA.w + xrA.w + w * weA.w) * atA.w +
            lrelu(xlB.x + xrB.x + w * weB.x) * atB.x +
            lrelu(xlB.y + xrB.y + w * weB.y) * atB.y +
            lrelu(xlB.z + xrB.z + w * weB.z) * atB.z +
            lrelu(xlB.w + xrB.w + w * weB.w) * atB.w;
#pragma unroll
        for (int off = 16; off; off >>= 1)
            part += __shfl_xor_sync(0xffffffffu, part, off);
        float nm = fmaxf(m, part);
        float corr = __expf(m - nm);
        float p = __expf(part - nm);
        s = s * corr + p;
        accA.x = accA.x * corr + p * xlA.x;  accA.y = accA.y * corr + p * xlA.y;
        accA.z = accA.z * corr + p * xlA.z;  accA.w = accA.w * corr + p * xlA.w;
        accB.x = accB.x * corr + p * xlB.x;  accB.y = accB.y * corr + p * xlB.y;
        accB.z = accB.z * corr + p * xlB.z;  accB.w = accB.w * corr + p * xlB.w;
        m = nm;
    }
    float inv = 1.f / (s + 1e-16f);
    float4 bA = *(const float4*)(bias1 + c0);
    float4 bB = *(const float4*)(bias1 + c1);
    float4 pA = *(const float4*)(prelu1 + c0);
    float4 pB = *(const float4*)(prelu1 + c1);
    float4 skA = *(const float4*)(d_skp + (size_t)n * EMBD + c0);
    float4 skB = *(const float4*)(d_skp + (size_t)n * EMBD + c1);

    float o;
    float4 rA, rB;
    o = accA.x * inv + bA.x + skA.x; rA.x = o >= 0.f ? o : pA.x * o;
    o = accA.y * inv + bA.y + skA.y; rA.y = o >= 0.f ? o : pA.y * o;
    o = accA.z * inv + bA.z + skA.z; rA.z = o >= 0.f ? o : pA.z * o;
    o = accA.w * inv + bA.w + skA.w; rA.w = o >= 0.f ? o : pA.w * o;
    o = accB.x * inv + bB.x + skB.x; rB.x = o >= 0.f ? o : pB.x * o;
    o = accB.y * inv + bB.y + skB.y; rB.y = o >= 0.f ? o : pB.y * o;
    o = accB.z * inv + bB.z + skB.z; rB.z = o >= 0.f ? o : pB.z * o;
    o = accB.w * inv + bB.w + skB.w; rB.w = o >= 0.f ? o : pB.w * o;
    *(float4*)(out + (size_t)n * EMBD + c0) = rA;
    *(float4*)(out + (size_t)n * EMBD + c1) = rB;
}

// ---------------- launch -------------------------------------------------------
extern "C" void kernel_launch(void* const* d_in, const int* in_sizes, int n_in,
                              void* d_out, int out_size) {
    const float* x      = (const float*)d_in[0];
    const float* ew     = (const float*)d_in[1];
    const float* Wl0    = (const float*)d_in[2];
    const float* bl0    = (const float*)d_in[3];
    const float* Wr0    = (const float*)d_in[4];
    const float* br0    = (const float*)d_in[5];
    const float* We0    = (const float*)d_in[6];
    const float* att0   = (const float*)d_in[7];
    const float* bias0  = (const float*)d_in[8];
    const float* Wl1    = (const float*)d_in[9];
    const float* bl1    = (const float*)d_in[10];
    const float* Wr1    = (const float*)d_in[11];
    const float* br1    = (const float*)d_in[12];
    const float* We1    = (const float*)d_in[13];
    const float* att1   = (const float*)d_in[14];
    const float* bias1  = (const float*)d_in[15];
    const float* skipW  = (const float*)d_in[16];
    const float* skipb  = (const float*)d_in[17];
    const float* prelu0 = (const float*)d_in[18];
    const float* prelu1 = (const float*)d_in[19];
    const int*   eidx   = (const int*)d_in[20];
    float* out = (float*)d_out;

    float *xl0p, *xr0p, *xl1p, *xr1p, *skpp;
    uint32_t *xh, *xlo, *h0h, *h0l;
    uint32_t *wl0h, *wl0l, *wr0h, *wr0l, *wl1h, *wl1l, *wr1h, *wr1l, *wsh, *wsl;
    cudaGetSymbolAddress((void**)&xl0p, d_xl0);
    cudaGetSymbolAddress((void**)&xr0p, d_xr0);
    cudaGetSymbolAddress((void**)&xl1p, d_xl1);
    cudaGetSymbolAddress((void**)&xr1p, d_xr1);
    cudaGetSymbolAddress((void**)&skpp, d_skp);
    cudaGetSymbolAddress((void**)&xh,  d_xh);
    cudaGetSymbolAddress((void**)&xlo, d_xlo);
    cudaGetSymbolAddress((void**)&h0h, d_h0h);
    cudaGetSymbolAddress((void**)&h0l, d_h0l);
    cudaGetSymbolAddress((void**)&wl0h, d_Wl0h); cudaGetSymbolAddress((void**)&wl0l, d_Wl0l);
    cudaGetSymbolAddress((void**)&wr0h, d_Wr0h); cudaGetSymbolAddress((void**)&wr0l, d_Wr0l);
    cudaGetSymbolAddress((void**)&wl1h, d_Wl1h); cudaGetSymbolAddress((void**)&wl1l, d_Wl1l);
    cudaGetSymbolAddress((void**)&wr1h, d_Wr1h); cudaGetSymbolAddress((void**)&wr1l, d_Wr1l);
    cudaGetSymbolAddress((void**)&wsh,  d_Wsh);  cudaGetSymbolAddress((void**)&wsl,  d_Wsl);

    const int MB = (NN + 127) / 128;

    // graph build
    zero_init_kernel<<<(NN + 255) / 256, 256>>>();
    hist_kernel<<<(EE + 255) / 256, 256>>>(eidx, ew);
    scan_kernel<<<1, 1024>>>();
    scatter_kernel<<<(ETOT + 255) / 256, 256>>>(eidx, ew);

    // operand splits
    {
        int nw = NN * IND / 2;
        split_rows_kernel<<<(nw + 255) / 256, 256>>>(x, xh, xlo, nw);
    }
    split_B_kernel<<<(IND / 2 * H0D + 255) / 256, 256>>>(Wl0, wl0h, wl0l, IND, H0D);
    split_B_kernel<<<(IND / 2 * H0D + 255) / 256, 256>>>(Wr0, wr0h, wr0l, IND, H0D);
    split_B_kernel<<<(H0D / 2 * EMBD + 255) / 256, 256>>>(Wl1, wl1h, wl1l, H0D, EMBD);
    split_B_kernel<<<(H0D / 2 * EMBD + 255) / 256, 256>>>(Wr1, wr1h, wr1l, H0D, EMBD);
    split_B_kernel<<<(IND / 2 * EMBD + 255) / 256, 256>>>(skipW, wsh, wsl, IND, EMBD);

    // layer 0 projections (bf16x3 tensor cores)
    gemm_bf16x3<<<dim3(H0D / 64, MB), 128>>>(xh, xlo, wl0h, wl0l, bl0, xl0p, NN, IND, H0D);
    gemm_bf16x3<<<dim3(H0D / 64, MB), 128>>>(xh, xlo, wr0h, wr0l, br0, xr0p, NN, IND, H0D);

    // layer 0 attention + aggregate + bias + PReLU (writes split h0)
    gat0_kernel<<<NN, 128>>>(We0, att0, bias0, prelu0);

    // layer 1 projections + skip
    gemm_bf16x3<<<dim3(EMBD / 64, MB), 128>>>(h0h, h0l, wl1h, wl1l, bl1, xl1p, NN, H0D, EMBD);
    gemm_bf16x3<<<dim3(EMBD / 64, MB), 128>>>(h0h, h0l, wr1h, wr1l, br1, xr1p, NN, H0D, EMBD);
    gemm_bf16x3<<<dim3(EMBD / 64, MB), 128>>>(xh, xlo, wsh, wsl, skipb, skpp, NN, IND, EMBD);

    // layer 1 attention + aggregate + bias + skip + PReLU -> out
    gat1_kernel<<<(NN * 32 + 255) / 256, 256>>>(We1, att1, bias1, prelu1, out);

    (void)in_sizes; (void)n_in; (void)out_size;
}

// round 9
// speedup vs baseline: 1.8985x; 1.0682x over previous
#include <cuda_runtime.h>
#include <cstdint>

#define NN   10000
#define EE   160000
#define IND  256
#define H0D  512      // 4 heads * 128
#define EMBD 256
#define ETOT (EE + NN)

// ---------------- scratch (device globals; no allocations allowed) ------------
__device__ float d_wsum[NN];
__device__ int   d_cnt[NN];
__device__ int   d_rowptr[NN + 1];
__device__ int   d_fill[NN];
__device__ int   d_csrc[ETOT];
__device__ float d_cw[ETOT];
__device__ __align__(16) float d_xlr0[(size_t)NN * 1024];  // [xl0 | xr0]
__device__ __align__(16) float d_xlr1[(size_t)NN * 512];   // [xl1 | xr1]
__device__ __align__(16) float d_skp [(size_t)NN * EMBD];

// packed bf16x2 hi/lo operands
__device__ __align__(16) uint32_t d_xh [(size_t)NN * IND / 2];
__device__ __align__(16) uint32_t d_xlo[(size_t)NN * IND / 2];
__device__ __align__(16) uint32_t d_h0h[(size_t)NN * H0D / 2];
__device__ __align__(16) uint32_t d_h0l[(size_t)NN * H0D / 2];
__device__ __align__(16) uint32_t d_Wl0h[IND * H0D / 2], d_Wl0l[IND * H0D / 2];
__device__ __align__(16) uint32_t d_Wr0h[IND * H0D / 2], d_Wr0l[IND * H0D / 2];
__device__ __align__(16) uint32_t d_Wl1h[H0D * EMBD / 2], d_Wl1l[H0D * EMBD / 2];
__device__ __align__(16) uint32_t d_Wr1h[H0D * EMBD / 2], d_Wr1l[H0D * EMBD / 2];
__device__ __align__(16) uint32_t d_Wsh [IND * EMBD / 2], d_Wsl [IND * EMBD / 2];

// ---------------- bf16 split helpers -------------------------------------------
__device__ __forceinline__ uint32_t pack_bf2(float even_, float odd_) {
    uint32_t w;
    asm("cvt.rn.bf16x2.f32 %0, %1, %2;" : "=r"(w) : "f"(odd_), "f"(even_));
    return w;
}
__device__ __forceinline__ float bf_lo(uint32_t w) { return __uint_as_float(w << 16); }
__device__ __forceinline__ float bf_hi(uint32_t w) { return __uint_as_float(w & 0xffff0000u); }

__device__ __forceinline__ void split2(float f0, float f1, uint32_t& hi, uint32_t& lo) {
    hi = pack_bf2(f0, f1);
    lo = pack_bf2(f0 - bf_lo(hi), f1 - bf_hi(hi));
}

// A-format: row-major [M][K] -> packed words [M][K/2] (consecutive-k pairs)
__global__ void split_rows_kernel(const float* __restrict__ A,
                                  uint32_t* __restrict__ Hh, uint32_t* __restrict__ Hl,
                                  int nwords) {
    int i = blockIdx.x * blockDim.x + threadIdx.x;
    if (i >= nwords) return;
    float2 f = ((const float2*)A)[i];
    uint32_t hi, lo;
    split2(f.x, f.y, hi, lo);
    Hh[i] = hi; Hl[i] = lo;
}

// B-format: [K][N] -> k-pair interleaved words [K/2][N]
__global__ void split_B_kernel(const float* __restrict__ B,
                               uint32_t* __restrict__ Bh, uint32_t* __restrict__ Bl,
                               int K, int N) {
    int i = blockIdx.x * blockDim.x + threadIdx.x;
    int total = (K >> 1) * N;
    if (i >= total) return;
    int k2 = i / N, n = i - k2 * N;
    float f0 = B[(size_t)(2 * k2) * N + n];
    float f1 = B[(size_t)(2 * k2 + 1) * N + n];
    uint32_t hi, lo;
    split2(f0, f1, hi, lo);
    Bh[i] = hi; Bl[i] = lo;
}

// ---------------- small utility kernels ---------------------------------------
__global__ void zero_init_kernel() {
    int i = blockIdx.x * blockDim.x + threadIdx.x;
    if (i < NN) { d_wsum[i] = 0.f; d_cnt[i] = 0; d_fill[i] = 0; }
}

__global__ void hist_kernel(const int* __restrict__ eidx, const float* __restrict__ ew) {
    int e = blockIdx.x * blockDim.x + threadIdx.x;
    if (e < EE) {
        int d = eidx[EE + e];
        atomicAdd(&d_cnt[d], 1);
        atomicAdd(&d_wsum[d], ew[e]);
    }
}

__global__ void scan_kernel() {
    __shared__ int sh[1024];
    const int CH = 10;
    int t = threadIdx.x;
    int base = t * CH;
    int loc[CH];
    int run = 0;
#pragma unroll
    for (int i = 0; i < CH; i++) {
        int idx = base + i;
        int c = (idx < NN) ? (d_cnt[idx] + 1) : 0;
        run += c;
        loc[i] = run;
    }
    sh[t] = run;
    __syncthreads();
    for (int off = 1; off < 1024; off <<= 1) {
        int v = (t >= off) ? sh[t - off] : 0;
        __syncthreads();
        sh[t] += v;
        __syncthreads();
    }
    int excl = sh[t] - run;
#pragma unroll
    for (int i = 0; i < CH; i++) {
        int idx = base + i;
        if (idx < NN) d_rowptr[idx + 1] = excl + loc[i];
    }
    if (t == 0) d_rowptr[0] = 0;
}

__global__ void scatter_kernel(const int* __restrict__ eidx, const float* __restrict__ ew) {
    int e = blockIdx.x * blockDim.x + threadIdx.x;
    if (e >= ETOT) return;
    int s, d; float w;
    if (e < EE) {
        s = eidx[e]; d = eidx[EE + e]; w = ew[e];
    } else {
        int n = e - EE;
        s = n; d = n;
        int c = d_cnt[n];
        w = (c > 0) ? (d_wsum[n] / (float)c) : 0.f;
    }
    int pos = d_rowptr[d] + atomicAdd(&d_fill[d], 1);
    d_csrc[pos] = s;
    d_cw[pos]   = w;
}

// ---------------- bf16x3 tensor-core GEMM (merged dual-B) ----------------------
// C[M,N] = A[M,K] @ [B0|B1][K,N] + [bias0|bias1][N]; hi*hi + lo*hi + hi*lo.
// BM=128, BN=64, BK=16, 128 threads (4 warps 2x2), warp tile 64x32.

__device__ __forceinline__ void mma16(float* c, const uint32_t* a, const uint32_t* b) {
    asm volatile(
        "mma.sync.aligned.m16n8k16.row.col.f32.bf16.bf16.f32 "
        "{%0,%1,%2,%3}, {%4,%5,%6,%7}, {%8,%9}, {%0,%1,%2,%3};"
        : "+f"(c[0]), "+f"(c[1]), "+f"(c[2]), "+f"(c[3])
        : "r"(a[0]), "r"(a[1]), "r"(a[2]), "r"(a[3]), "r"(b[0]), "r"(b[1]));
}

#define ASTR2 136
#define BSTR2 72

__global__ __launch_bounds__(128)
void gemm_bf16x3(const uint32_t* __restrict__ Ah, const uint32_t* __restrict__ Al,
                 const uint32_t* __restrict__ B0h, const uint32_t* __restrict__ B0l,
                 const uint32_t* __restrict__ B1h, const uint32_t* __restrict__ B1l,
                 const float* __restrict__ bias0, const float* __restrict__ bias1,
                 int nsplit, float* __restrict__ C,
                 int M, int K, int N) {
    __shared__ uint32_t Ahs[2][8][ASTR2];
    __shared__ uint32_t Als[2][8][ASTR2];
    __shared__ uint32_t Bhs[2][8][BSTR2];
    __shared__ uint32_t Bls[2][8][BSTR2];

    const int tid  = threadIdx.x;
    const int warp = tid >> 5;
    const int lane = tid & 31;
    const int r = lane >> 2;
    const int q = lane & 3;

    const int warp_m = (warp & 1) * 64;
    const int warp_n = (warp >> 1) * 32;
    const int m0 = blockIdx.y * 128;
    const int n0 = blockIdx.x * 64;
    const int Kw = K >> 1;

    // select B segment (block-uniform; nsplit % 64 == 0)
    const uint32_t* Bh; const uint32_t* Bl; const float* bsrc; int bstride, nc0;
    if (n0 < nsplit) { Bh = B0h; Bl = B0l; bsrc = bias0; bstride = nsplit;     nc0 = n0; }
    else             { Bh = B1h; Bl = B1l; bsrc = bias1; bstride = N - nsplit; nc0 = n0 - nsplit; }

    float acc[4][4][4];
#pragma unroll
    for (int i = 0; i < 4; i++)
#pragma unroll
        for (int j = 0; j < 4; j++)
#pragma unroll
            for (int k = 0; k < 4; k++) acc[i][j][k] = 0.f;

    const int am = m0 + tid;
    const bool avalid = (am < M);
    const int brow = tid >> 4;
    const int bcolw = (tid & 15) * 4;

    const int nstages = K >> 4;
    const uint4 z4 = make_uint4(0u, 0u, 0u, 0u);

    uint4 ahA, ahB, alA, alB, bh4, bl4;

    {
        const uint32_t* ap  = Ah + (size_t)am * Kw;
        const uint32_t* alp = Al + (size_t)am * Kw;
        ahA = avalid ? *(const uint4*)(ap) : z4;
        ahB = avalid ? *(const uint4*)(ap + 4) : z4;
        alA = avalid ? *(const uint4*)(alp) : z4;
        alB = avalid ? *(const uint4*)(alp + 4) : z4;
        const uint32_t* bp  = Bh + (size_t)brow * bstride + nc0 + bcolw;
        const uint32_t* blp = Bl + (size_t)brow * bstride + nc0 + bcolw;
        bh4 = *(const uint4*)bp;
        bl4 = *(const uint4*)blp;
    }
    {
        Ahs[0][0][tid] = ahA.x; Ahs[0][1][tid] = ahA.y; Ahs[0][2][tid] = ahA.z; Ahs[0][3][tid] = ahA.w;
        Ahs[0][4][tid] = ahB.x; Ahs[0][5][tid] = ahB.y; Ahs[0][6][tid] = ahB.z; Ahs[0][7][tid] = ahB.w;
        Als[0][0][tid] = alA.x; Als[0][1][tid] = alA.y; Als[0][2][tid] = alA.z; Als[0][3][tid] = alA.w;
        Als[0][4][tid] = alB.x; Als[0][5][tid] = alB.y; Als[0][6][tid] = alB.z; Als[0][7][tid] = alB.w;
        *(uint4*)&Bhs[0][brow][bcolw] = bh4;
        *(uint4*)&Bls[0][brow][bcolw] = bl4;
    }
    __syncthreads();

    for (int s = 0; s < nstages; s++) {
        const int buf = s & 1;
        if (s + 1 < nstages) {
            const int w0 = (s + 1) * 8;
            const uint32_t* ap  = Ah + (size_t)am * Kw + w0;
            const uint32_t* alp = Al + (size_t)am * Kw + w0;
            ahA = avalid ? *(const uint4*)(ap) : z4;
            ahB = avalid ? *(const uint4*)(ap + 4) : z4;
            alA = avalid ? *(const uint4*)(alp) : z4;
            alB = avalid ? *(const uint4*)(alp + 4) : z4;
            const uint32_t* bp  = Bh + (size_t)(w0 + brow) * bstride + nc0 + bcolw;
            const uint32_t* blp = Bl + (size_t)(w0 + brow) * bstride + nc0 + bcolw;
            bh4 = *(const uint4*)bp;
            bl4 = *(const uint4*)blp;
        }

        uint32_t ah[4][4], al[4][4];
#pragma unroll
        for (int mt = 0; mt < 4; mt++) {
            const int mm = warp_m + mt * 16;
            ah[mt][0] = Ahs[buf][q][mm + r];
            ah[mt][1] = Ahs[buf][q][mm + r + 8];
            ah[mt][2] = Ahs[buf][q + 4][mm + r];
            ah[mt][3] = Ahs[buf][q + 4][mm + r + 8];
            al[mt][0] = Als[buf][q][mm + r];
            al[mt][1] = Als[buf][q][mm + r + 8];
            al[mt][2] = Als[buf][q + 4][mm + r];
            al[mt][3] = Als[buf][q + 4][mm + r + 8];
        }
        uint32_t bh[4][2], bl[4][2];
#pragma unroll
        for (int nt = 0; nt < 4; nt++) {
            const int nn = warp_n + nt * 8;
            bh[nt][0] = Bhs[buf][q][nn + r];
            bh[nt][1] = Bhs[buf][q + 4][nn + r];
            bl[nt][0] = Bls[buf][q][nn + r];
            bl[nt][1] = Bls[buf][q + 4][nn + r];
        }
#pragma unroll
        for (int mt = 0; mt < 4; mt++)
#pragma unroll
            for (int nt = 0; nt < 4; nt++) {
                mma16(acc[mt][nt], ah[mt], bh[nt]);
                mma16(acc[mt][nt], al[mt], bh[nt]);
                mma16(acc[mt][nt], ah[mt], bl[nt]);
            }

        if (s + 1 < nstages) {
            const int nb = (s + 1) & 1;
            Ahs[nb][0][tid] = ahA.x; Ahs[nb][1][tid] = ahA.y; Ahs[nb][2][tid] = ahA.z; Ahs[nb][3][tid] = ahA.w;
            Ahs[nb][4][tid] = ahB.x; Ahs[nb][5][tid] = ahB.y; Ahs[nb][6][tid] = ahB.z; Ahs[nb][7][tid] = ahB.w;
            Als[nb][0][tid] = alA.x; Als[nb][1][tid] = alA.y; Als[nb][2][tid] = alA.z; Als[nb][3][tid] = alA.w;
            Als[nb][4][tid] = alB.x; Als[nb][5][tid] = alB.y; Als[nb][6][tid] = alB.z; Als[nb][7][tid] = alB.w;
            *(uint4*)&Bhs[nb][brow][bcolw] = bh4;
            *(uint4*)&Bls[nb][brow][bcolw] = bl4;
        }
        __syncthreads();
    }

#pragma unroll
    for (int mt = 0; mt < 4; mt++) {
#pragma unroll
        for (int nt = 0; nt < 4; nt++) {
            const int col = n0 + warp_n + nt * 8 + 2 * q;
            const int bcol = (col - n0) + nc0;
            const float bx = bsrc[bcol];
            const float by = bsrc[bcol + 1];
            const int row0 = m0 + warp_m + mt * 16 + r;
            const int row1 = row0 + 8;
            if (row0 < M) {
                float2 v = make_float2(acc[mt][nt][0] + bx, acc[mt][nt][1] + by);
                *(float2*)(C + (size_t)row0 * N + col) = v;
            }
            if (row1 < M) {
                float2 v = make_float2(acc[mt][nt][2] + bx, acc[mt][nt][3] + by);
                *(float2*)(C + (size_t)row1 * N + col) = v;
            }
        }
    }
}

// ---------------- GAT layer 0: 4 heads x 128, block per node -------------------
__device__ __forceinline__ float lrelu(float v) { return v >= 0.f ? v : 0.2f * v; }

__global__ __launch_bounds__(128)
void gat0_kernel(const float* __restrict__ We0, const float* __restrict__ att0,
                 const float* __restrict__ bias0, const float* __restrict__ prelu0) {
    int n = blockIdx.x;
    int lane = threadIdx.x & 31;
    int h = threadIdx.x >> 5;
    int c = h * 128 + lane * 4;

    float4 we = *(const float4*)(We0 + c);
    float4 at = *(const float4*)(att0 + c);
    float4 xr = *(const float4*)(d_xlr0 + (size_t)n * 1024 + 512 + c);

    int rs = d_rowptr[n], re = d_rowptr[n + 1];
    float m = -1e30f, s = 0.f;
    float4 acc = make_float4(0.f, 0.f, 0.f, 0.f);

    for (int e = rs; e < re; e++) {
        int src = d_csrc[e];
        float w = d_cw[e];
        float4 xl = *(const float4*)(d_xlr0 + (size_t)src * 1024 + c);
        float vx = lrelu(xl.x + xr.x + w * we.x);
        float vy = lrelu(xl.y + xr.y + w * we.y);
        float vz = lrelu(xl.z + xr.z + w * we.z);
        float vw = lrelu(xl.w + xr.w + w * we.w);
        float part = vx * at.x + vy * at.y + vz * at.z + vw * at.w;
#pragma unroll
        for (int off = 16; off; off >>= 1)
            part += __shfl_xor_sync(0xffffffffu, part, off);
        float nm = fmaxf(m, part);
        float corr = __expf(m - nm);
        float p = __expf(part - nm);
        s = s * corr + p;
        acc.x = acc.x * corr + p * xl.x;
        acc.y = acc.y * corr + p * xl.y;
        acc.z = acc.z * corr + p * xl.z;
        acc.w = acc.w * corr + p * xl.w;
        m = nm;
    }
    float inv = 1.f / (s + 1e-16f);
    float4 b = *(const float4*)(bias0 + c);
    float4 pr = *(const float4*)(prelu0 + c);
    float ox = acc.x * inv + b.x; ox = ox >= 0.f ? ox : pr.x * ox;
    float oy = acc.y * inv + b.y; oy = oy >= 0.f ? oy : pr.y * oy;
    float oz = acc.z * inv + b.z; oz = oz >= 0.f ? oz : pr.z * oz;
    float ow = acc.w * inv + b.w; ow = ow >= 0.f ? ow : pr.w * ow;

    // write h0 directly in split bf16 hi/lo packed form (layer-1 A operand)
    uint32_t w0h, w0l, w1h, w1l;
    split2(ox, oy, w0h, w0l);
    split2(oz, ow, w1h, w1l);
    size_t widx = ((size_t)n * H0D + c) >> 1;
    *(uint2*)(d_h0h + widx) = make_uint2(w0h, w1h);
    *(uint2*)(d_h0l + widx) = make_uint2(w0l, w1l);
}

// ---------------- GAT layer 1: 1 head x 256, warp per node ---------------------
__global__ __launch_bounds__(256)
void gat1_kernel(const float* __restrict__ We1, const float* __restrict__ att1,
                 const float* __restrict__ bias1, const float* __restrict__ prelu1,
                 float* __restrict__ out) {
    int gw = (blockIdx.x * blockDim.x + threadIdx.x) >> 5;
    if (gw >= NN) return;
    int n = gw;
    int lane = threadIdx.x & 31;
    int c0 = lane * 4, c1 = 128 + lane * 4;

    float4 weA = *(const float4*)(We1 + c0);
    float4 weB = *(const float4*)(We1 + c1);
    float4 atA = *(const float4*)(att1 + c0);
    float4 atB = *(const float4*)(att1 + c1);
    float4 xrA = *(const float4*)(d_xlr1 + (size_t)n * 512 + 256 + c0);
    float4 xrB = *(const float4*)(d_xlr1 + (size_t)n * 512 + 256 + c1);

    int rs = d_rowptr[n], re = d_rowptr[n + 1];
    float m = -1e30f, s = 0.f;
    float4 accA = make_float4(0.f, 0.f, 0.f, 0.f);
    float4 accB = make_float4(0.f, 0.f, 0.f, 0.f);

    for (int e = rs; e < re; e++) {
        int src = d_csrc[e];
        float w = d_cw[e];
        float4 xlA = *(const float4*)(d_xlr1 + (size_t)src * 512 + c0);
        float4 xlB = *(const float4*)(d_xlr1 + (size_t)src * 512 + c1);
        float part =
            lrelu(xlA.x + xrA.x + w * weA.x) * atA.x +
            lrelu(xlA.y + xrA.y + w * weA.y) * atA.y +
            lrelu(xlA.z + xrA.z + w * weA.z) * atA.z +
            lrelu(xlA.w + xrA.w + w * weA.w) * atA.w +
            lrelu(xlB.x + xrB.x + w * weB.x) * atB.x +
            lrelu(xlB.y + xrB.y + w * weB.y) * atB.y +
            lrelu(xlB.z + xrB.z + w * weB.z) * atB.z +
            lrelu(xlB.w + xrB.w + w * weB.w) * atB.w;
#pragma unroll
        for (int off = 16; off; off >>= 1)
            part += __shfl_xor_sync(0xffffffffu, part, off);
        float nm = fmaxf(m, part);
        float corr = __expf(m - nm);
        float p = __expf(part - nm);
        s = s * corr + p;
        accA.x = accA.x * corr + p * xlA.x;  accA.y = accA.y * corr + p * xlA.y;
        accA.z = accA.z * corr + p * xlA.z;  accA.w = accA.w * corr + p * xlA.w;
        accB.x = accB.x * corr + p * xlB.x;  accB.y = accB.y * corr + p * xlB.y;
        accB.z = accB.z * corr + p * xlB.z;  accB.w = accB.w * corr + p * xlB.w;
        m = nm;
    }
    float inv = 1.f / (s + 1e-16f);
    float4 bA = *(const float4*)(bias1 + c0);
    float4 bB = *(const float4*)(bias1 + c1);
    float4 pA = *(const float4*)(prelu1 + c0);
    float4 pB = *(const float4*)(prelu1 + c1);
    float4 skA = *(const float4*)(d_skp + (size_t)n * EMBD + c0);
    float4 skB = *(const float4*)(d_skp + (size_t)n * EMBD + c1);

    float o;
    float4 rA, rB;
    o = accA.x * inv + bA.x + skA.x; rA.x = o >= 0.f ? o : pA.x * o;
    o = accA.y * inv + bA.y + skA.y; rA.y = o >= 0.f ? o : pA.y * o;
    o = accA.z * inv + bA.z + skA.z; rA.z = o >= 0.f ? o : pA.z * o;
    o = accA.w * inv + bA.w + skA.w; rA.w = o >= 0.f ? o : pA.w * o;
    o = accB.x * inv + bB.x + skB.x; rB.x = o >= 0.f ? o : pB.x * o;
    o = accB.y * inv + bB.y + skB.y; rB.y = o >= 0.f ? o : pB.y * o;
    o = accB.z * inv + bB.z + skB.z; rB.z = o >= 0.f ? o : pB.z * o;
    o = accB.w * inv + bB.w + skB.w; rB.w = o >= 0.f ? o : pB.w * o;
    *(float4*)(out + (size_t)n * EMBD + c0) = rA;
    *(float4*)(out + (size_t)n * EMBD + c1) = rB;
}

// ---------------- launch -------------------------------------------------------
extern "C" void kernel_launch(void* const* d_in, const int* in_sizes, int n_in,
                              void* d_out, int out_size) {
    const float* x      = (const float*)d_in[0];
    const float* ew     = (const float*)d_in[1];
    const float* Wl0    = (const float*)d_in[2];
    const float* bl0    = (const float*)d_in[3];
    const float* Wr0    = (const float*)d_in[4];
    const float* br0    = (const float*)d_in[5];
    const float* We0    = (const float*)d_in[6];
    const float* att0   = (const float*)d_in[7];
    const float* bias0  = (const float*)d_in[8];
    const float* Wl1    = (const float*)d_in[9];
    const float* bl1    = (const float*)d_in[10];
    const float* Wr1    = (const float*)d_in[11];
    const float* br1    = (const float*)d_in[12];
    const float* We1    = (const float*)d_in[13];
    const float* att1   = (const float*)d_in[14];
    const float* bias1  = (const float*)d_in[15];
    const float* skipW  = (const float*)d_in[16];
    const float* skipb  = (const float*)d_in[17];
    const float* prelu0 = (const float*)d_in[18];
    const float* prelu1 = (const float*)d_in[19];
    const int*   eidx   = (const int*)d_in[20];
    float* out = (float*)d_out;

    float *xlr0p, *xlr1p, *skpp;
    uint32_t *xh, *xlo, *h0h, *h0l;
    uint32_t *wl0h, *wl0l, *wr0h, *wr0l, *wl1h, *wl1l, *wr1h, *wr1l, *wsh, *wsl;
    cudaGetSymbolAddress((void**)&xlr0p, d_xlr0);
    cudaGetSymbolAddress((void**)&xlr1p, d_xlr1);
    cudaGetSymbolAddress((void**)&skpp,  d_skp);
    cudaGetSymbolAddress((void**)&xh,  d_xh);
    cudaGetSymbolAddress((void**)&xlo, d_xlo);
    cudaGetSymbolAddress((void**)&h0h, d_h0h);
    cudaGetSymbolAddress((void**)&h0l, d_h0l);
    cudaGetSymbolAddress((void**)&wl0h, d_Wl0h); cudaGetSymbolAddress((void**)&wl0l, d_Wl0l);
    cudaGetSymbolAddress((void**)&wr0h, d_Wr0h); cudaGetSymbolAddress((void**)&wr0l, d_Wr0l);
    cudaGetSymbolAddress((void**)&wl1h, d_Wl1h); cudaGetSymbolAddress((void**)&wl1l, d_Wl1l);
    cudaGetSymbolAddress((void**)&wr1h, d_Wr1h); cudaGetSymbolAddress((void**)&wr1l, d_Wr1l);
    cudaGetSymbolAddress((void**)&wsh,  d_Wsh);  cudaGetSymbolAddress((void**)&wsl,  d_Wsl);

    const int MB = (NN + 127) / 128;  // 79

    // launches 1-3: operand splits for layer 0 (so launch 4 = big GEMM -> ncu target)
    {
        int nw = NN * IND / 2;
        split_rows_kernel<<<(nw + 255) / 256, 256>>>(x, xh, xlo, nw);
    }
    split_B_kernel<<<(IND / 2 * H0D + 255) / 256, 256>>>(Wl0, wl0h, wl0l, IND, H0D);
    split_B_kernel<<<(IND / 2 * H0D + 255) / 256, 256>>>(Wr0, wr0h, wr0l, IND, H0D);

    // launch 4: merged layer-0 projections x @ [Wl0|Wr0] -> d_xlr0 [NN][1024]
    gemm_bf16x3<<<dim3(1024 / 64, MB), 128>>>(
        xh, xlo, wl0h, wl0l, wr0h, wr0l, bl0, br0, 512, xlr0p, NN, IND, 1024);

    // graph build (needed before gat0)
    zero_init_kernel<<<(NN + 255) / 256, 256>>>();
    hist_kernel<<<(EE + 255) / 256, 256>>>(eidx, ew);
    scan_kernel<<<1, 1024>>>();
    scatter_kernel<<<(ETOT + 255) / 256, 256>>>(eidx, ew);

    // remaining weight splits (independent; after gemm0 to keep launch-4 alignment)
    split_B_kernel<<<(H0D / 2 * EMBD + 255) / 256, 256>>>(Wl1, wl1h, wl1l, H0D, EMBD);
    split_B_kernel<<<(H0D / 2 * EMBD + 255) / 256, 256>>>(Wr1, wr1h, wr1l, H0D, EMBD);
    split_B_kernel<<<(IND / 2 * EMBD + 255) / 256, 256>>>(skipW, wsh, wsl, IND, EMBD);

    // layer 0 attention + aggregate + bias + PReLU (writes split h0)
    gat0_kernel<<<NN, 128>>>(We0, att0, bias0, prelu0);

    // merged layer-1 projections h0 @ [Wl1|Wr1] -> d_xlr1 [NN][512]
    gemm_bf16x3<<<dim3(512 / 64, MB), 128>>>(
        h0h, h0l, wl1h, wl1l, wr1h, wr1l, bl1, br1, 256, xlr1p, NN, H0D, 512);

    // skip: x @ skipW -> d_skp [NN][256]
    gemm_bf16x3<<<dim3(256 / 64, MB), 128>>>(
        xh, xlo, wsh, wsl, wsh, wsl, skipb, skipb, 256, skpp, NN, IND, 256);

    // layer 1 attention + aggregate + bias + skip + PReLU -> out
    gat1_kernel<<<(NN * 32 + 255) / 256, 256>>>(We1, att1, bias1, prelu1, out);

    (void)in_sizes; (void)n_in; (void)out_size;
}

// round 10
// speedup vs baseline: 2.0102x; 1.0588x over previous
#include <cuda_runtime.h>
#include <cstdint>

#define NN   10000
#define EE   160000
#define IND  256
#define H0D  512      // 4 heads * 128
#define EMBD 256
#define ETOT (EE + NN)

// ---------------- scratch (device globals; no allocations allowed) ------------
__device__ float d_wsum[NN];
__device__ int   d_cnt[NN];
__device__ int   d_rowptr[NN + 1];
__device__ int   d_fill[NN];
__device__ int   d_csrc[ETOT];
__device__ float d_cw[ETOT];
__device__ __align__(16) float d_xlr0[(size_t)NN * 1024];  // [xl0 | xr0]
__device__ __align__(16) float d_xlr1[(size_t)NN * 512];   // [xl1 | xr1]
__device__ __align__(16) float d_skp [(size_t)NN * EMBD];

// packed bf16x2 hi/lo operands
__device__ __align__(16) uint32_t d_xh [(size_t)NN * IND / 2];
__device__ __align__(16) uint32_t d_xlo[(size_t)NN * IND / 2];
__device__ __align__(16) uint32_t d_h0h[(size_t)NN * H0D / 2];
__device__ __align__(16) uint32_t d_h0l[(size_t)NN * H0D / 2];
__device__ __align__(16) uint32_t d_Wl0h[IND * H0D / 2], d_Wl0l[IND * H0D / 2];
__device__ __align__(16) uint32_t d_Wr0h[IND * H0D / 2], d_Wr0l[IND * H0D / 2];
__device__ __align__(16) uint32_t d_Wl1h[H0D * EMBD / 2], d_Wl1l[H0D * EMBD / 2];
__device__ __align__(16) uint32_t d_Wr1h[H0D * EMBD / 2], d_Wr1l[H0D * EMBD / 2];
__device__ __align__(16) uint32_t d_Wsh [IND * EMBD / 2], d_Wsl [IND * EMBD / 2];

// ---------------- bf16 split helpers -------------------------------------------
__device__ __forceinline__ uint32_t pack_bf2(float even_, float odd_) {
    uint32_t w;
    asm("cvt.rn.bf16x2.f32 %0, %1, %2;" : "=r"(w) : "f"(odd_), "f"(even_));
    return w;
}
__device__ __forceinline__ float bf_lo(uint32_t w) { return __uint_as_float(w << 16); }
__device__ __forceinline__ float bf_hi(uint32_t w) { return __uint_as_float(w & 0xffff0000u); }

__device__ __forceinline__ void split2(float f0, float f1, uint32_t& hi, uint32_t& lo) {
    hi = pack_bf2(f0, f1);
    lo = pack_bf2(f0 - bf_lo(hi), f1 - bf_hi(hi));
}

// A-format: row-major [M][K] -> packed words [M][K/2] (consecutive-k pairs)
__global__ void split_rows_kernel(const float* __restrict__ A,
                                  uint32_t* __restrict__ Hh, uint32_t* __restrict__ Hl,
                                  int nwords) {
    int i = blockIdx.x * blockDim.x + threadIdx.x;
    if (i >= nwords) return;
    float2 f = ((const float2*)A)[i];
    uint32_t hi, lo;
    split2(f.x, f.y, hi, lo);
    Hh[i] = hi; Hl[i] = lo;
}

// B-format: [K][N] -> k-pair interleaved words [K/2][N]
__global__ void split_B_kernel(const float* __restrict__ B,
                               uint32_t* __restrict__ Bh, uint32_t* __restrict__ Bl,
                               int K, int N) {
    int i = blockIdx.x * blockDim.x + threadIdx.x;
    int total = (K >> 1) * N;
    if (i >= total) return;
    int k2 = i / N, n = i - k2 * N;
    float f0 = B[(size_t)(2 * k2) * N + n];
    float f1 = B[(size_t)(2 * k2 + 1) * N + n];
    uint32_t hi, lo;
    split2(f0, f1, hi, lo);
    Bh[i] = hi; Bl[i] = lo;
}

// ---------------- small utility kernels ---------------------------------------
__global__ void zero_init_kernel() {
    int i = blockIdx.x * blockDim.x + threadIdx.x;
    if (i < NN) { d_wsum[i] = 0.f; d_cnt[i] = 0; d_fill[i] = 0; }
}

__global__ void hist_kernel(const int* __restrict__ eidx, const float* __restrict__ ew) {
    int e = blockIdx.x * blockDim.x + threadIdx.x;
    if (e < EE) {
        int d = eidx[EE + e];
        atomicAdd(&d_cnt[d], 1);
        atomicAdd(&d_wsum[d], ew[e]);
    }
}

__global__ void scan_kernel() {
    __shared__ int sh[1024];
    const int CH = 10;
    int t = threadIdx.x;
    int base = t * CH;
    int loc[CH];
    int run = 0;
#pragma unroll
    for (int i = 0; i < CH; i++) {
        int idx = base + i;
        int c = (idx < NN) ? (d_cnt[idx] + 1) : 0;
        run += c;
        loc[i] = run;
    }
    sh[t] = run;
    __syncthreads();
    for (int off = 1; off < 1024; off <<= 1) {
        int v = (t >= off) ? sh[t - off] : 0;
        __syncthreads();
        sh[t] += v;
        __syncthreads();
    }
    int excl = sh[t] - run;
#pragma unroll
    for (int i = 0; i < CH; i++) {
        int idx = base + i;
        if (idx < NN) d_rowptr[idx + 1] = excl + loc[i];
    }
    if (t == 0) d_rowptr[0] = 0;
}

__global__ void scatter_kernel(const int* __restrict__ eidx, const float* __restrict__ ew) {
    int e = blockIdx.x * blockDim.x + threadIdx.x;
    if (e >= ETOT) return;
    int s, d; float w;
    if (e < EE) {
        s = eidx[e]; d = eidx[EE + e]; w = ew[e];
    } else {
        int n = e - EE;
        s = n; d = n;
        int c = d_cnt[n];
        w = (c > 0) ? (d_wsum[n] / (float)c) : 0.f;
    }
    int pos = d_rowptr[d] + atomicAdd(&d_fill[d], 1);
    d_csrc[pos] = s;
    d_cw[pos]   = w;
}

// ---------------- bf16x3 tensor-core GEMM (merged dual-B, 64x64 warp tile) -----
// C[M,N] = A[M,K] @ [B0|B1][K,N] + [bias0|bias1][N]; hi*hi + lo*hi + hi*lo.
// BM=128, BN=128, BK=16, 128 threads (4 warps 2x2), warp tile 64x64.

__device__ __forceinline__ void mma16(float* c, const uint32_t* a, const uint32_t* b) {
    asm volatile(
        "mma.sync.aligned.m16n8k16.row.col.f32.bf16.bf16.f32 "
        "{%0,%1,%2,%3}, {%4,%5,%6,%7}, {%8,%9}, {%0,%1,%2,%3};"
        : "+f"(c[0]), "+f"(c[1]), "+f"(c[2]), "+f"(c[3])
        : "r"(a[0]), "r"(a[1]), "r"(a[2]), "r"(a[3]), "r"(b[0]), "r"(b[1]));
}

#define ASTR2 136
#define BSTR2 136

__global__ __launch_bounds__(128)
void gemm_bf16x3(const uint32_t* __restrict__ Ah, const uint32_t* __restrict__ Al,
                 const uint32_t* __restrict__ B0h, const uint32_t* __restrict__ B0l,
                 const uint32_t* __restrict__ B1h, const uint32_t* __restrict__ B1l,
                 const float* __restrict__ bias0, const float* __restrict__ bias1,
                 int nsplit, float* __restrict__ C,
                 int M, int K, int N) {
    __shared__ uint32_t Ahs[2][8][ASTR2];
    __shared__ uint32_t Als[2][8][ASTR2];
    __shared__ uint32_t Bhs[2][8][BSTR2];
    __shared__ uint32_t Bls[2][8][BSTR2];

    const int tid  = threadIdx.x;
    const int warp = tid >> 5;
    const int lane = tid & 31;
    const int r = lane >> 2;
    const int q = lane & 3;

    const int warp_m = (warp & 1) * 64;
    const int warp_n = (warp >> 1) * 64;
    const int m0 = blockIdx.y * 128;
    const int n0 = blockIdx.x * 128;
    const int Kw = K >> 1;

    // select B segment (block-uniform; nsplit % 128 == 0)
    const uint32_t* Bh; const uint32_t* Bl; const float* bsrc; int bstride, nc0;
    if (n0 < nsplit) { Bh = B0h; Bl = B0l; bsrc = bias0; bstride = nsplit;     nc0 = n0; }
    else             { Bh = B1h; Bl = B1l; bsrc = bias1; bstride = N - nsplit; nc0 = n0 - nsplit; }

    float acc[4][8][4];
#pragma unroll
    for (int i = 0; i < 4; i++)
#pragma unroll
        for (int j = 0; j < 8; j++)
#pragma unroll
            for (int k = 0; k < 4; k++) acc[i][j][k] = 0.f;

    const int am = m0 + tid;
    const bool avalid = (am < M);
    const int brow = tid >> 4;            // 0..7  (k2 row)
    const int bcolw = (tid & 15) * 8;     // 0..120 word col

    const int nstages = K >> 4;
    const uint4 z4 = make_uint4(0u, 0u, 0u, 0u);

    uint4 ahA, ahB, alA, alB, bhA, bhB, blA, blB;

    // prologue: load stage 0
    {
        const uint32_t* ap  = Ah + (size_t)am * Kw;
        const uint32_t* alp = Al + (size_t)am * Kw;
        ahA = avalid ? *(const uint4*)(ap) : z4;
        ahB = avalid ? *(const uint4*)(ap + 4) : z4;
        alA = avalid ? *(const uint4*)(alp) : z4;
        alB = avalid ? *(const uint4*)(alp + 4) : z4;
        const uint32_t* bp  = Bh + (size_t)brow * bstride + nc0 + bcolw;
        const uint32_t* blp = Bl + (size_t)brow * bstride + nc0 + bcolw;
        bhA = *(const uint4*)(bp);
        bhB = *(const uint4*)(bp + 4);
        blA = *(const uint4*)(blp);
        blB = *(const uint4*)(blp + 4);
    }
    {
        Ahs[0][0][tid] = ahA.x; Ahs[0][1][tid] = ahA.y; Ahs[0][2][tid] = ahA.z; Ahs[0][3][tid] = ahA.w;
        Ahs[0][4][tid] = ahB.x; Ahs[0][5][tid] = ahB.y; Ahs[0][6][tid] = ahB.z; Ahs[0][7][tid] = ahB.w;
        Als[0][0][tid] = alA.x; Als[0][1][tid] = alA.y; Als[0][2][tid] = alA.z; Als[0][3][tid] = alA.w;
        Als[0][4][tid] = alB.x; Als[0][5][tid] = alB.y; Als[0][6][tid] = alB.z; Als[0][7][tid] = alB.w;
        *(uint4*)&Bhs[0][brow][bcolw]     = bhA;
        *(uint4*)&Bhs[0][brow][bcolw + 4] = bhB;
        *(uint4*)&Bls[0][brow][bcolw]     = blA;
        *(uint4*)&Bls[0][brow][bcolw + 4] = blB;
    }
    __syncthreads();

    for (int s = 0; s < nstages; s++) {
        const int buf = s & 1;
        // prefetch next stage into regs
        if (s + 1 < nstages) {
            const int w0 = (s + 1) * 8;
            const uint32_t* ap  = Ah + (size_t)am * Kw + w0;
            const uint32_t* alp = Al + (size_t)am * Kw + w0;
            ahA = avalid ? *(const uint4*)(ap) : z4;
            ahB = avalid ? *(const uint4*)(ap + 4) : z4;
            alA = avalid ? *(const uint4*)(alp) : z4;
            alB = avalid ? *(const uint4*)(alp + 4) : z4;
            const uint32_t* bp  = Bh + (size_t)(w0 + brow) * bstride + nc0 + bcolw;
            const uint32_t* blp = Bl + (size_t)(w0 + brow) * bstride + nc0 + bcolw;
            bhA = *(const uint4*)(bp);
            bhB = *(const uint4*)(bp + 4);
            blA = *(const uint4*)(blp);
            blB = *(const uint4*)(blp + 4);
        }

        // B fragments for this stage (8 n-tiles, hi+lo)
        uint32_t bh[8][2], bl[8][2];
#pragma unroll
        for (int nt = 0; nt < 8; nt++) {
            const int nn = warp_n + nt * 8;
            bh[nt][0] = Bhs[buf][q][nn + r];
            bh[nt][1] = Bhs[buf][q + 4][nn + r];
            bl[nt][0] = Bls[buf][q][nn + r];
            bl[nt][1] = Bls[buf][q + 4][nn + r];
        }

        // stream A fragments per m-tile; 24 MMAs each
#pragma unroll
        for (int mt = 0; mt < 4; mt++) {
            const int mm = warp_m + mt * 16;
            uint32_t ah[4], al[4];
            ah[0] = Ahs[buf][q][mm + r];
            ah[1] = Ahs[buf][q][mm + r + 8];
            ah[2] = Ahs[buf][q + 4][mm + r];
            ah[3] = Ahs[buf][q + 4][mm + r + 8];
            al[0] = Als[buf][q][mm + r];
            al[1] = Als[buf][q][mm + r + 8];
            al[2] = Als[buf][q + 4][mm + r];
            al[3] = Als[buf][q + 4][mm + r + 8];
#pragma unroll
            for (int nt = 0; nt < 8; nt++) {
                mma16(acc[mt][nt], ah, bh[nt]);
                mma16(acc[mt][nt], al, bh[nt]);
                mma16(acc[mt][nt], ah, bl[nt]);
            }
        }

        // store prefetched stage
        if (s + 1 < nstages) {
            const int nb = (s + 1) & 1;
            Ahs[nb][0][tid] = ahA.x; Ahs[nb][1][tid] = ahA.y; Ahs[nb][2][tid] = ahA.z; Ahs[nb][3][tid] = ahA.w;
            Ahs[nb][4][tid] = ahB.x; Ahs[nb][5][tid] = ahB.y; Ahs[nb][6][tid] = ahB.z; Ahs[nb][7][tid] = ahB.w;
            Als[nb][0][tid] = alA.x; Als[nb][1][tid] = alA.y; Als[nb][2][tid] = alA.z; Als[nb][3][tid] = alA.w;
            Als[nb][4][tid] = alB.x; Als[nb][5][tid] = alB.y; Als[nb][6][tid] = alB.z; Als[nb][7][tid] = alB.w;
            *(uint4*)&Bhs[nb][brow][bcolw]     = bhA;
            *(uint4*)&Bhs[nb][brow][bcolw + 4] = bhB;
            *(uint4*)&Bls[nb][brow][bcolw]     = blA;
            *(uint4*)&Bls[nb][brow][bcolw + 4] = blB;
        }
        __syncthreads();
    }

    // epilogue: C[m][n] = acc + bias[n]
#pragma unroll
    for (int mt = 0; mt < 4; mt++) {
#pragma unroll
        for (int nt = 0; nt < 8; nt++) {
            const int coff = warp_n + nt * 8 + 2 * q;   // within block
            const int col  = n0 + coff;
            const float bx = bsrc[nc0 + coff];
            const float by = bsrc[nc0 + coff + 1];
            const int row0 = m0 + warp_m + mt * 16 + r;
            const int row1 = row0 + 8;
            if (row0 < M) {
                float2 v = make_float2(acc[mt][nt][0] + bx, acc[mt][nt][1] + by);
                *(float2*)(C + (size_t)row0 * N + col) = v;
            }
            if (row1 < M) {
                float2 v = make_float2(acc[mt][nt][2] + bx, acc[mt][nt][3] + by);
                *(float2*)(C + (size_t)row1 * N + col) = v;
            }
        }
    }
}

// ---------------- GAT layer 0: 4 heads x 128, block per node -------------------
__device__ __forceinline__ float lrelu(float v) { return v >= 0.f ? v : 0.2f * v; }

__global__ __launch_bounds__(128)
void gat0_kernel(const float* __restrict__ We0, const float* __restrict__ att0,
                 const float* __restrict__ bias0, const float* __restrict__ prelu0) {
    int n = blockIdx.x;
    int lane = threadIdx.x & 31;
    int h = threadIdx.x >> 5;
    int c = h * 128 + lane * 4;

    float4 we = *(const float4*)(We0 + c);
    float4 at = *(const float4*)(att0 + c);
    float4 xr = *(const float4*)(d_xlr0 + (size_t)n * 1024 + 512 + c);

    int rs = d_rowptr[n], re = d_rowptr[n + 1];
    float m = -1e30f, s = 0.f;
    float4 acc = make_float4(0.f, 0.f, 0.f, 0.f);

    for (int e = rs; e < re; e++) {
        int src = d_csrc[e];
        float w = d_cw[e];
        float4 xl = *(const float4*)(d_xlr0 + (size_t)src * 1024 + c);
        float vx = lrelu(xl.x + xr.x + w * we.x);
        float vy = lrelu(xl.y + xr.y + w * we.y);
        float vz = lrelu(xl.z + xr.z + w * we.z);
        float vw = lrelu(xl.w + xr.w + w * we.w);
        float part = vx * at.x + vy * at.y + vz * at.z + vw * at.w;
#pragma unroll
        for (int off = 16; off; off >>= 1)
            part += __shfl_xor_sync(0xffffffffu, part, off);
        float nm = fmaxf(m, part);
        float corr = __expf(m - nm);
        float p = __expf(part - nm);
        s = s * corr + p;
        acc.x = acc.x * corr + p * xl.x;
        acc.y = acc.y * corr + p * xl.y;
        acc.z = acc.z * corr + p * xl.z;
        acc.w = acc.w * corr + p * xl.w;
        m = nm;
    }
    float inv = 1.f / (s + 1e-16f);
    float4 b = *(const float4*)(bias0 + c);
    float4 pr = *(const float4*)(prelu0 + c);
    float ox = acc.x * inv + b.x; ox = ox >= 0.f ? ox : pr.x * ox;
    float oy = acc.y * inv + b.y; oy = oy >= 0.f ? oy : pr.y * oy;
    float oz = acc.z * inv + b.z; oz = oz >= 0.f ? oz : pr.z * oz;
    float ow = acc.w * inv + b.w; ow = ow >= 0.f ? ow : pr.w * ow;

    // write h0 directly in split bf16 hi/lo packed form (layer-1 A operand)
    uint32_t w0h, w0l, w1h, w1l;
    split2(ox, oy, w0h, w0l);
    split2(oz, ow, w1h, w1l);
    size_t widx = ((size_t)n * H0D + c) >> 1;
    *(uint2*)(d_h0h + widx) = make_uint2(w0h, w1h);
    *(uint2*)(d_h0l + widx) = make_uint2(w0l, w1l);
}

// ---------------- GAT layer 1: 1 head x 256, warp per node ---------------------
__global__ __launch_bounds__(256)
void gat1_kernel(const float* __restrict__ We1, const float* __restrict__ att1,
                 const float* __restrict__ bias1, const float* __restrict__ prelu1,
                 float* __restrict__ out) {
    int gw = (blockIdx.x * blockDim.x + threadIdx.x) >> 5;
    if (gw >= NN) return;
    int n = gw;
    int lane = threadIdx.x & 31;
    int c0 = lane * 4, c1 = 128 + lane * 4;

    float4 weA = *(const float4*)(We1 + c0);
    float4 weB = *(const float4*)(We1 + c1);
    float4 atA = *(const float4*)(att1 + c0);
    float4 atB = *(const float4*)(att1 + c1);
    float4 xrA = *(const float4*)(d_xlr1 + (size_t)n * 512 + 256 + c0);
    float4 xrB = *(const float4*)(d_xlr1 + (size_t)n * 512 + 256 + c1);

    int rs = d_rowptr[n], re = d_rowptr[n + 1];
    float m = -1e30f, s = 0.f;
    float4 accA = make_float4(0.f, 0.f, 0.f, 0.f);
    float4 accB = make_float4(0.f, 0.f, 0.f, 0.f);

    for (int e = rs; e < re; e++) {
        int src = d_csrc[e];
        float w = d_cw[e];
        float4 xlA = *(const float4*)(d_xlr1 + (size_t)src * 512 + c0);
        float4 xlB = *(const float4*)(d_xlr1 + (size_t)src * 512 + c1);
        float part =
            lrelu(xlA.x + xrA.x + w * weA.x) * atA.x +
            lrelu(xlA.y + xrA.y + w * weA.y) * atA.y +
            lrelu(xlA.z + xrA.z + w * weA.z) * atA.z +
            lrelu(xlA.w + xrA.w + w * weA.w) * atA.w +
            lrelu(xlB.x + xrB.x + w * weB.x) * atB.x +
            lrelu(xlB.y + xrB.y + w * weB.y) * atB.y +
            lrelu(xlB.z + xrB.z + w * weB.z) * atB.z +
            lrelu(xlB.w + xrB.w + w * weB.w) * atB.w;
#pragma unroll
        for (int off = 16; off; off >>= 1)
            part += __shfl_xor_sync(0xffffffffu, part, off);
        float nm = fmaxf(m, part);
        float corr = __expf(m - nm);
        float p = __expf(part - nm);
        s = s * corr + p;
        accA.x = accA.x * corr + p * xlA.x;  accA.y = accA.y * corr + p * xlA.y;
        accA.z = accA.z * corr + p * xlA.z;  accA.w = accA.w * corr + p * xlA.w;
        accB.x = accB.x * corr + p * xlB.x;  accB.y = accB.y * corr + p * xlB.y;
        accB.z = accB.z * corr + p * xlB.z;  accB.w = accB.w * corr + p * xlB.w;
        m = nm;
    }
    float inv = 1.f / (s + 1e-16f);
    float4 bA = *(const float4*)(bias1 + c0);
    float4 bB = *(const float4*)(bias1 + c1);
    float4 pA = *(const float4*)(prelu1 + c0);
    float4 pB = *(const float4*)(prelu1 + c1);
    float4 skA = *(const float4*)(d_skp + (size_t)n * EMBD + c0);
    float4 skB = *(const float4*)(d_skp + (size_t)n * EMBD + c1);

    float o;
    float4 rA, rB;
    o = accA.x * inv + bA.x + skA.x; rA.x = o >= 0.f ? o : pA.x * o;
    o = accA.y * inv + bA.y + skA.y; rA.y = o >= 0.f ? o : pA.y * o;
    o = accA.z * inv + bA.z + skA.z; rA.z = o >= 0.f ? o : pA.z * o;
    o = accA.w * inv + bA.w + skA.w; rA.w = o >= 0.f ? o : pA.w * o;
    o = accB.x * inv + bB.x + skB.x; rB.x = o >= 0.f ? o : pB.x * o;
    o = accB.y * inv + bB.y + skB.y; rB.y = o >= 0.f ? o : pB.y * o;
    o = accB.z * inv + bB.z + skB.z; rB.z = o >= 0.f ? o : pB.z * o;
    o = accB.w * inv + bB.w + skB.w; rB.w = o >= 0.f ? o : pB.w * o;
    *(float4*)(out + (size_t)n * EMBD + c0) = rA;
    *(float4*)(out + (size_t)n * EMBD + c1) = rB;
}

// ---------------- launch -------------------------------------------------------
extern "C" void kernel_launch(void* const* d_in, const int* in_sizes, int n_in,
                              void* d_out, int out_size) {
    const float* x      = (const float*)d_in[0];
    const float* ew     = (const float*)d_in[1];
    const float* Wl0    = (const float*)d_in[2];
    const float* bl0    = (const float*)d_in[3];
    const float* Wr0    = (const float*)d_in[4];
    const float* br0    = (const float*)d_in[5];
    const float* We0    = (const float*)d_in[6];
    const float* att0   = (const float*)d_in[7];
    const float* bias0  = (const float*)d_in[8];
    const float* Wl1    = (const float*)d_in[9];
    const float* bl1    = (const float*)d_in[10];
    const float* Wr1    = (const float*)d_in[11];
    const float* br1    = (const float*)d_in[12];
    const float* We1    = (const float*)d_in[13];
    const float* att1   = (const float*)d_in[14];
    const float* bias1  = (const float*)d_in[15];
    const float* skipW  = (const float*)d_in[16];
    const float* skipb  = (const float*)d_in[17];
    const float* prelu0 = (const float*)d_in[18];
    const float* prelu1 = (const float*)d_in[19];
    const int*   eidx   = (const int*)d_in[20];
    float* out = (float*)d_out;

    float *xlr0p, *xlr1p, *skpp;
    uint32_t *xh, *xlo, *h0h, *h0l;
    uint32_t *wl0h, *wl0l, *wr0h, *wr0l, *wl1h, *wl1l, *wr1h, *wr1l, *wsh, *wsl;
    cudaGetSymbolAddress((void**)&xlr0p, d_xlr0);
    cudaGetSymbolAddress((void**)&xlr1p, d_xlr1);
    cudaGetSymbolAddress((void**)&skpp,  d_skp);
    cudaGetSymbolAddress((void**)&xh,  d_xh);
    cudaGetSymbolAddress((void**)&xlo, d_xlo);
    cudaGetSymbolAddress((void**)&h0h, d_h0h);
    cudaGetSymbolAddress((void**)&h0l, d_h0l);
    cudaGetSymbolAddress((void**)&wl0h, d_Wl0h); cudaGetSymbolAddress((void**)&wl0l, d_Wl0l);
    cudaGetSymbolAddress((void**)&wr0h, d_Wr0h); cudaGetSymbolAddress((void**)&wr0l, d_Wr0l);
    cudaGetSymbolAddress((void**)&wl1h, d_Wl1h); cudaGetSymbolAddress((void**)&wl1l, d_Wl1l);
    cudaGetSymbolAddress((void**)&wr1h, d_Wr1h); cudaGetSymbolAddress((void**)&wr1l, d_Wr1l);
    cudaGetSymbolAddress((void**)&wsh,  d_Wsh);  cudaGetSymbolAddress((void**)&wsl,  d_Wsl);

    const int MB = (NN + 127) / 128;  // 79

    // launches 1-3: operand splits for layer 0 (so launch 4 = big GEMM -> ncu target)
    {
        int nw = NN * IND / 2;
        split_rows_kernel<<<(nw + 255) / 256, 256>>>(x, xh, xlo, nw);
    }
    split_B_kernel<<<(IND / 2 * H0D + 255) / 256, 256>>>(Wl0, wl0h, wl0l, IND, H0D);
    split_B_kernel<<<(IND / 2 * H0D + 255) / 256, 256>>>(Wr0, wr0h, wr0l, IND, H0D);

    // launch 4: merged layer-0 projections x @ [Wl0|Wr0] -> d_xlr0 [NN][1024]
    gemm_bf16x3<<<dim3(1024 / 128, MB), 128>>>(
        xh, xlo, wl0h, wl0l, wr0h, wr0l, bl0, br0, 512, xlr0p, NN, IND, 1024);

    // graph build (needed before gat0)
    zero_init_kernel<<<(NN + 255) / 256, 256>>>();
    hist_kernel<<<(EE + 255) / 256, 256>>>(eidx, ew);
    scan_kernel<<<1, 1024>>>();
    scatter_kernel<<<(ETOT + 255) / 256, 256>>>(eidx, ew);

    // remaining weight splits (independent; after gemm0 to keep launch-4 alignment)
    split_B_kernel<<<(H0D / 2 * EMBD + 255) / 256, 256>>>(Wl1, wl1h, wl1l, H0D, EMBD);
    split_B_kernel<<<(H0D / 2 * EMBD + 255) / 256, 256>>>(Wr1, wr1h, wr1l, H0D, EMBD);
    split_B_kernel<<<(IND / 2 * EMBD + 255) / 256, 256>>>(skipW, wsh, wsl, IND, EMBD);

    // layer 0 attention + aggregate + bias + PReLU (writes split h0)
    gat0_kernel<<<NN, 128>>>(We0, att0, bias0, prelu0);

    // merged layer-1 projections h0 @ [Wl1|Wr1] -> d_xlr1 [NN][512]
    gemm_bf16x3<<<dim3(512 / 128, MB), 128>>>(
        h0h, h0l, wl1h, wl1l, wr1h, wr1l, bl1, br1, 256, xlr1p, NN, H0D, 512);

    // skip: x @ skipW -> d_skp [NN][256]
    gemm_bf16x3<<<dim3(256 / 128, MB), 128>>>(
        xh, xlo, wsh, wsl, wsh, wsl, skipb, skipb, 256, skpp, NN, IND, 256);

    // layer 1 attention + aggregate + bias + skip + PReLU -> out
    gat1_kernel<<<(NN * 32 + 255) / 256, 256>>>(We1, att1, bias1, prelu1, out);

    (void)in_sizes; (void)n_in; (void)out_size;
}

// round 11
// speedup vs baseline: 2.0813x; 1.0353x over previous
#include <cuda_runtime.h>
#include <cstdint>

#define NN   10000
#define EE   160000
#define IND  256
#define H0D  512      // 4 heads * 128
#define EMBD 256
#define ETOT (EE + NN)

// ---------------- scratch (device globals; no allocations allowed) ------------
__device__ float d_wsum[NN];
__device__ int   d_cnt[NN];
__device__ int   d_rowptr[NN + 1];
__device__ int   d_fill[NN];
__device__ int   d_csrc[ETOT];
__device__ float d_cw[ETOT];
__device__ __align__(16) float d_xlr0[(size_t)NN * 1024];  // [xl0 | xr0]
__device__ __align__(16) float d_xlr1[(size_t)NN * 512];   // [xl1 | xr1]
__device__ __align__(16) float d_skp [(size_t)NN * EMBD];

// packed bf16x2 hi/lo operands
__device__ __align__(16) uint32_t d_xh [(size_t)NN * IND / 2];
__device__ __align__(16) uint32_t d_xlo[(size_t)NN * IND / 2];
__device__ __align__(16) uint32_t d_h0h[(size_t)NN * H0D / 2];
__device__ __align__(16) uint32_t d_h0l[(size_t)NN * H0D / 2];
__device__ __align__(16) uint32_t d_Wl0h[IND * H0D / 2], d_Wl0l[IND * H0D / 2];
__device__ __align__(16) uint32_t d_Wr0h[IND * H0D / 2], d_Wr0l[IND * H0D / 2];
__device__ __align__(16) uint32_t d_Wl1h[H0D * EMBD / 2], d_Wl1l[H0D * EMBD / 2];
__device__ __align__(16) uint32_t d_Wr1h[H0D * EMBD / 2], d_Wr1l[H0D * EMBD / 2];
__device__ __align__(16) uint32_t d_Wsh [IND * EMBD / 2], d_Wsl [IND * EMBD / 2];

// ---------------- bf16 split helpers -------------------------------------------
__device__ __forceinline__ uint32_t pack_bf2(float even_, float odd_) {
    uint32_t w;
    asm("cvt.rn.bf16x2.f32 %0, %1, %2;" : "=r"(w) : "f"(odd_), "f"(even_));
    return w;
}
__device__ __forceinline__ float bf_lo(uint32_t w) { return __uint_as_float(w << 16); }
__device__ __forceinline__ float bf_hi(uint32_t w) { return __uint_as_float(w & 0xffff0000u); }

__device__ __forceinline__ void split2(float f0, float f1, uint32_t& hi, uint32_t& lo) {
    hi = pack_bf2(f0, f1);
    lo = pack_bf2(f0 - bf_lo(hi), f1 - bf_hi(hi));
}

// A-format: row-major [M][K] -> packed words [M][K/2] (consecutive-k pairs)
__global__ void split_rows_kernel(const float* __restrict__ A,
                                  uint32_t* __restrict__ Hh, uint32_t* __restrict__ Hl,
                                  int nwords) {
    int i = blockIdx.x * blockDim.x + threadIdx.x;
    if (i >= nwords) return;
    float2 f = ((const float2*)A)[i];
    uint32_t hi, lo;
    split2(f.x, f.y, hi, lo);
    Hh[i] = hi; Hl[i] = lo;
}

// B-format: [K][N] -> k-pair interleaved words [K/2][N]
__global__ void split_B_kernel(const float* __restrict__ B,
                               uint32_t* __restrict__ Bh, uint32_t* __restrict__ Bl,
                               int K, int N) {
    int i = blockIdx.x * blockDim.x + threadIdx.x;
    int total = (K >> 1) * N;
    if (i >= total) return;
    int k2 = i / N, n = i - k2 * N;
    float f0 = B[(size_t)(2 * k2) * N + n];
    float f1 = B[(size_t)(2 * k2 + 1) * N + n];
    uint32_t hi, lo;
    split2(f0, f1, hi, lo);
    Bh[i] = hi; Bl[i] = lo;
}

// ---------------- small utility kernels ---------------------------------------
__global__ void zero_init_kernel() {
    int i = blockIdx.x * blockDim.x + threadIdx.x;
    if (i < NN) { d_wsum[i] = 0.f; d_cnt[i] = 0; d_fill[i] = 0; }
}

__global__ void hist_kernel(const int* __restrict__ eidx, const float* __restrict__ ew) {
    int e = blockIdx.x * blockDim.x + threadIdx.x;
    if (e < EE) {
        int d = eidx[EE + e];
        atomicAdd(&d_cnt[d], 1);
        atomicAdd(&d_wsum[d], ew[e]);
    }
}

__global__ void scan_kernel() {
    __shared__ int sh[1024];
    const int CH = 10;
    int t = threadIdx.x;
    int base = t * CH;
    int loc[CH];
    int run = 0;
#pragma unroll
    for (int i = 0; i < CH; i++) {
        int idx = base + i;
        int c = (idx < NN) ? (d_cnt[idx] + 1) : 0;
        run += c;
        loc[i] = run;
    }
    sh[t] = run;
    __syncthreads();
    for (int off = 1; off < 1024; off <<= 1) {
        int v = (t >= off) ? sh[t - off] : 0;
        __syncthreads();
        sh[t] += v;
        __syncthreads();
    }
    int excl = sh[t] - run;
#pragma unroll
    for (int i = 0; i < CH; i++) {
        int idx = base + i;
        if (idx < NN) d_rowptr[idx + 1] = excl + loc[i];
    }
    if (t == 0) d_rowptr[0] = 0;
}

__global__ void scatter_kernel(const int* __restrict__ eidx, const float* __restrict__ ew) {
    int e = blockIdx.x * blockDim.x + threadIdx.x;
    if (e >= ETOT) return;
    int s, d; float w;
    if (e < EE) {
        s = eidx[e]; d = eidx[EE + e]; w = ew[e];
    } else {
        int n = e - EE;
        s = n; d = n;
        int c = d_cnt[n];
        w = (c > 0) ? (d_wsum[n] / (float)c) : 0.f;
    }
    int pos = d_rowptr[d] + atomicAdd(&d_fill[d], 1);
    d_csrc[pos] = s;
    d_cw[pos]   = w;
}

// ---------------- bf16x3 tensor-core GEMM (cp.async 4-stage pipeline) ----------
// C[M,N] = A[M,K] @ [B0|B1][K,N] + [bias0|bias1][N]; hi*hi + lo*hi + hi*lo.
// BM=128, BN=128, BK=16, 128 threads (4 warps 2x2), warp tile 64x64.

__device__ __forceinline__ void mma16(float* c, const uint32_t* a, const uint32_t* b) {
    asm volatile(
        "mma.sync.aligned.m16n8k16.row.col.f32.bf16.bf16.f32 "
        "{%0,%1,%2,%3}, {%4,%5,%6,%7}, {%8,%9}, {%0,%1,%2,%3};"
        : "+f"(c[0]), "+f"(c[1]), "+f"(c[2]), "+f"(c[3])
        : "r"(a[0]), "r"(a[1]), "r"(a[2]), "r"(a[3]), "r"(b[0]), "r"(b[1]));
}

#define CP16(dst, src) \
    asm volatile("cp.async.cg.shared.global [%0], [%1], 16;" :: "r"(dst), "l"(src))
#define CP_COMMIT() asm volatile("cp.async.commit_group;" ::: "memory")
#define CP_WAIT(n)  asm volatile("cp.async.wait_group %0;" :: "n"(n) : "memory")

// stage layout (bytes): A-hi 128 rows x 12-word stride (8 data + 4 pad) = 6144,
// A-lo 6144, B-hi 8 rows x 136-word stride = 4352, B-lo 4352
#define NSTG     4
#define ST_AH    0
#define ST_AL    6144
#define ST_BH    12288
#define ST_BL    16640
#define ST_BYTES 20992
#define GEMM_DSMEM (NSTG * ST_BYTES)   // 83968
#define ARSTR 12
#define BRSTR 136

__global__ __launch_bounds__(128)
void gemm_bf16x3(const uint32_t* __restrict__ Ah, const uint32_t* __restrict__ Al,
                 const uint32_t* __restrict__ B0h, const uint32_t* __restrict__ B0l,
                 const uint32_t* __restrict__ B1h, const uint32_t* __restrict__ B1l,
                 const float* __restrict__ bias0, const float* __restrict__ bias1,
                 int nsplit, float* __restrict__ C,
                 int M, int K, int N) {
    extern __shared__ char smem[];
    const uint32_t s32 = (uint32_t)__cvta_generic_to_shared(smem);

    const int tid  = threadIdx.x;
    const int warp = tid >> 5;
    const int lane = tid & 31;
    const int r = lane >> 2;
    const int q = lane & 3;

    const int warp_m = (warp & 1) * 64;
    const int warp_n = (warp >> 1) * 64;
    const int m0 = blockIdx.y * 128;
    const int n0 = blockIdx.x * 128;
    const int Kw = K >> 1;

    // select B segment (block-uniform; nsplit % 128 == 0)
    const uint32_t* Bh; const uint32_t* Bl; const float* bsrc; int bstride, nc0;
    if (n0 < nsplit) { Bh = B0h; Bl = B0l; bsrc = bias0; bstride = nsplit;     nc0 = n0; }
    else             { Bh = B1h; Bl = B1l; bsrc = bias1; bstride = N - nsplit; nc0 = n0 - nsplit; }

    float acc[4][8][4];
#pragma unroll
    for (int i = 0; i < 4; i++)
#pragma unroll
        for (int j = 0; j < 8; j++)
#pragma unroll
            for (int k = 0; k < 4; k++) acc[i][j][k] = 0.f;

    int am = m0 + tid; if (am >= M) am = M - 1;   // clamp: extra rows never stored
    const int brow = tid >> 4;            // 0..7  (k2 row)
    const int bcw  = (tid & 15) * 8;      // 0..120 word col

    const uint32_t dA_h = s32 + ST_AH + tid * 48;
    const uint32_t dA_l = s32 + ST_AL + tid * 48;
    const uint32_t dB_h = s32 + ST_BH + brow * (BRSTR * 4) + (tid & 15) * 32;
    const uint32_t dB_l = s32 + ST_BL + brow * (BRSTR * 4) + (tid & 15) * 32;

    const int nstages = K >> 4;

    // issue cp.async for one k16 stage into ring slot st
    auto load_stage = [&](int st, int w0) {
        const uint32_t so = (uint32_t)(st * ST_BYTES);
        const uint32_t* ap  = Ah + (size_t)am * Kw + w0;
        const uint32_t* alp = Al + (size_t)am * Kw + w0;
        CP16(dA_h + so,      ap);
        CP16(dA_h + so + 16, ap + 4);
        CP16(dA_l + so,      alp);
        CP16(dA_l + so + 16, alp + 4);
        const uint32_t* bp  = Bh + (size_t)(w0 + brow) * bstride + nc0 + bcw;
        const uint32_t* blp = Bl + (size_t)(w0 + brow) * bstride + nc0 + bcw;
        CP16(dB_h + so,      bp);
        CP16(dB_h + so + 16, bp + 4);
        CP16(dB_l + so,      blp);
        CP16(dB_l + so + 16, blp + 4);
    };

    // prologue: stages 0..NSTG-2
#pragma unroll
    for (int s = 0; s < NSTG - 1; s++) {
        if (s < nstages) load_stage(s, s * 8);
        CP_COMMIT();
    }

    for (int st = 0; st < nstages; st++) {
        CP_WAIT(NSTG - 2);       // stage st arrived
        __syncthreads();         // + everyone done computing stage st-1

        const int nxt = st + NSTG - 1;
        if (nxt < nstages) load_stage(nxt % NSTG, nxt * 8);
        CP_COMMIT();

        const int buf = st % NSTG;
        const uint32_t* Ash = (const uint32_t*)(smem + buf * ST_BYTES + ST_AH);
        const uint32_t* Asl = (const uint32_t*)(smem + buf * ST_BYTES + ST_AL);
        const uint32_t* Bsh = (const uint32_t*)(smem + buf * ST_BYTES + ST_BH);
        const uint32_t* Bsl = (const uint32_t*)(smem + buf * ST_BYTES + ST_BL);

        // B fragments for this stage (8 n-tiles, hi+lo)
        uint32_t bh[8][2], bl[8][2];
#pragma unroll
        for (int nt = 0; nt < 8; nt++) {
            const int nn = warp_n + nt * 8 + r;
            bh[nt][0] = Bsh[q * BRSTR + nn];
            bh[nt][1] = Bsh[(q + 4) * BRSTR + nn];
            bl[nt][0] = Bsl[q * BRSTR + nn];
            bl[nt][1] = Bsl[(q + 4) * BRSTR + nn];
        }

        // stream A fragments per m-tile; 24 MMAs each
#pragma unroll
        for (int mt = 0; mt < 4; mt++) {
            const int mm = warp_m + mt * 16 + r;
            uint32_t ah[4], al[4];
            ah[0] = Ash[mm * ARSTR + q];
            ah[1] = Ash[(mm + 8) * ARSTR + q];
            ah[2] = Ash[mm * ARSTR + q + 4];
            ah[3] = Ash[(mm + 8) * ARSTR + q + 4];
            al[0] = Asl[mm * ARSTR + q];
            al[1] = Asl[(mm + 8) * ARSTR + q];
            al[2] = Asl[mm * ARSTR + q + 4];
            al[3] = Asl[(mm + 8) * ARSTR + q + 4];
#pragma unroll
            for (int nt = 0; nt < 8; nt++) {
                mma16(acc[mt][nt], ah, bh[nt]);
                mma16(acc[mt][nt], al, bh[nt]);
                mma16(acc[mt][nt], ah, bl[nt]);
            }
        }
    }

    // epilogue: C[m][n] = acc + bias[n]
#pragma unroll
    for (int mt = 0; mt < 4; mt++) {
#pragma unroll
        for (int nt = 0; nt < 8; nt++) {
            const int coff = warp_n + nt * 8 + 2 * q;   // within block
            const int col  = n0 + coff;
            const float bx = bsrc[nc0 + coff];
            const float by = bsrc[nc0 + coff + 1];
            const int row0 = m0 + warp_m + mt * 16 + r;
            const int row1 = row0 + 8;
            if (row0 < M) {
                float2 v = make_float2(acc[mt][nt][0] + bx, acc[mt][nt][1] + by);
                *(float2*)(C + (size_t)row0 * N + col) = v;
            }
            if (row1 < M) {
                float2 v = make_float2(acc[mt][nt][2] + bx, acc[mt][nt][3] + by);
                *(float2*)(C + (size_t)row1 * N + col) = v;
            }
        }
    }
}

// ---------------- GAT layer 0: 4 heads x 128, block per node -------------------
__device__ __forceinline__ float lrelu(float v) { return v >= 0.f ? v : 0.2f * v; }

__global__ __launch_bounds__(128)
void gat0_kernel(const float* __restrict__ We0, const float* __restrict__ att0,
                 const float* __restrict__ bias0, const float* __restrict__ prelu0) {
    int n = blockIdx.x;
    int lane = threadIdx.x & 31;
    int h = threadIdx.x >> 5;
    int c = h * 128 + lane * 4;

    float4 we = *(const float4*)(We0 + c);
    float4 at = *(const float4*)(att0 + c);
    float4 xr = *(const float4*)(d_xlr0 + (size_t)n * 1024 + 512 + c);

    int rs = d_rowptr[n], re = d_rowptr[n + 1];
    float m = -1e30f, s = 0.f;
    float4 acc = make_float4(0.f, 0.f, 0.f, 0.f);

    for (int e = rs; e < re; e++) {
        int src = d_csrc[e];
        float w = d_cw[e];
        float4 xl = *(const float4*)(d_xlr0 + (size_t)src * 1024 + c);
        float vx = lrelu(xl.x + xr.x + w * we.x);
        float vy = lrelu(xl.y + xr.y + w * we.y);
        float vz = lrelu(xl.z + xr.z + w * we.z);
        float vw = lrelu(xl.w + xr.w + w * we.w);
        float part = vx * at.x + vy * at.y + vz * at.z + vw * at.w;
#pragma unroll
        for (int off = 16; off; off >>= 1)
            part += __shfl_xor_sync(0xffffffffu, part, off);
        float nm = fmaxf(m, part);
        float corr = __expf(m - nm);
        float p = __expf(part - nm);
        s = s * corr + p;
        acc.x = acc.x * corr + p * xl.x;
        acc.y = acc.y * corr + p * xl.y;
        acc.z = acc.z * corr + p * xl.z;
        acc.w = acc.w * corr + p * xl.w;
        m = nm;
    }
    float inv = 1.f / (s + 1e-16f);
    float4 b = *(const float4*)(bias0 + c);
    float4 pr = *(const float4*)(prelu0 + c);
    float ox = acc.x * inv + b.x; ox = ox >= 0.f ? ox : pr.x * ox;
    float oy = acc.y * inv + b.y; oy = oy >= 0.f ? oy : pr.y * oy;
    float oz = acc.z * inv + b.z; oz = oz >= 0.f ? oz : pr.z * oz;
    float ow = acc.w * inv + b.w; ow = ow >= 0.f ? ow : pr.w * ow;

    // write h0 directly in split bf16 hi/lo packed form (layer-1 A operand)
    uint32_t w0h, w0l, w1h, w1l;
    split2(ox, oy, w0h, w0l);
    split2(oz, ow, w1h, w1l);
    size_t widx = ((size_t)n * H0D + c) >> 1;
    *(uint2*)(d_h0h + widx) = make_uint2(w0h, w1h);
    *(uint2*)(d_h0l + widx) = make_uint2(w0l, w1l);
}

// ---------------- GAT layer 1: 1 head x 256, warp per node ---------------------
__global__ __launch_bounds__(256)
void gat1_kernel(const float* __restrict__ We1, const float* __restrict__ att1,
                 const float* __restrict__ bias1, const float* __restrict__ prelu1,
                 float* __restrict__ out) {
    int gw = (blockIdx.x * blockDim.x + threadIdx.x) >> 5;
    if (gw >= NN) return;
    int n = gw;
    int lane = threadIdx.x & 31;
    int c0 = lane * 4, c1 = 128 + lane * 4;

    float4 weA = *(const float4*)(We1 + c0);
    float4 weB = *(const float4*)(We1 + c1);
    float4 atA = *(const float4*)(att1 + c0);
    float4 atB = *(const float4*)(att1 + c1);
    float4 xrA = *(const float4*)(d_xlr1 + (size_t)n * 512 + 256 + c0);
    float4 xrB = *(const float4*)(d_xlr1 + (size_t)n * 512 + 256 + c1);

    int rs = d_rowptr[n], re = d_rowptr[n + 1];
    float m = -1e30f, s = 0.f;
    float4 accA = make_float4(0.f, 0.f, 0.f, 0.f);
    float4 accB = make_float4(0.f, 0.f, 0.f, 0.f);

    for (int e = rs; e < re; e++) {
        int src = d_csrc[e];
        float w = d_cw[e];
        float4 xlA = *(const float4*)(d_xlr1 + (size_t)src * 512 + c0);
        float4 xlB = *(const float4*)(d_xlr1 + (size_t)src * 512 + c1);
        float part =
            lrelu(xlA.x + xrA.x + w * weA.x) * atA.x +
            lrelu(xlA.y + xrA.y + w * weA.y) * atA.y +
            lrelu(xlA.z + xrA.z + w * weA.z) * atA.z +
            lrelu(xlA.w + xrA.w + w * weA.w) * atA.w +
            lrelu(xlB.x + xrB.x + w * weB.x) * atB.x +
            lrelu(xlB.y + xrB.y + w * weB.y) * atB.y +
            lrelu(xlB.z + xrB.z + w * weB.z) * atB.z +
            lrelu(xlB.w + xrB.w + w * weB.w) * atB.w;
#pragma unroll
        for (int off = 16; off; off >>= 1)
            part += __shfl_xor_sync(0xffffffffu, part, off);
        float nm = fmaxf(m, part);
        float corr = __expf(m - nm);
        float p = __expf(part - nm);
        s = s * corr + p;
        accA.x = accA.x * corr + p * xlA.x;  accA.y = accA.y * corr + p * xlA.y;
        accA.z = accA.z * corr + p * xlA.z;  accA.w = accA.w * corr + p * xlA.w;
        accB.x = accB.x * corr + p * xlB.x;  accB.y = accB.y * corr + p * xlB.y;
        accB.z = accB.z * corr + p * xlB.z;  accB.w = accB.w * corr + p * xlB.w;
        m = nm;
    }
    float inv = 1.f / (s + 1e-16f);
    float4 bA = *(const float4*)(bias1 + c0);
    float4 bB = *(const float4*)(bias1 + c1);
    float4 pA = *(const float4*)(prelu1 + c0);
    float4 pB = *(const float4*)(prelu1 + c1);
    float4 skA = *(const float4*)(d_skp + (size_t)n * EMBD + c0);
    float4 skB = *(const float4*)(d_skp + (size_t)n * EMBD + c1);

    float o;
    float4 rA, rB;
    o = accA.x * inv + bA.x + skA.x; rA.x = o >= 0.f ? o : pA.x * o;
    o = accA.y * inv + bA.y + skA.y; rA.y = o >= 0.f ? o : pA.y * o;
    o = accA.z * inv + bA.z + skA.z; rA.z = o >= 0.f ? o : pA.z * o;
    o = accA.w * inv + bA.w + skA.w; rA.w = o >= 0.f ? o : pA.w * o;
    o = accB.x * inv + bB.x + skB.x; rB.x = o >= 0.f ? o : pB.x * o;
    o = accB.y * inv + bB.y + skB.y; rB.y = o >= 0.f ? o : pB.y * o;
    o = accB.z * inv + bB.z + skB.z; rB.z = o >= 0.f ? o : pB.z * o;
    o = accB.w * inv + bB.w + skB.w; rB.w = o >= 0.f ? o : pB.w * o;
    *(float4*)(out + (size_t)n * EMBD + c0) = rA;
    *(float4*)(out + (size_t)n * EMBD + c1) = rB;
}

// ---------------- launch -------------------------------------------------------
extern "C" void kernel_launch(void* const* d_in, const int* in_sizes, int n_in,
                              void* d_out, int out_size) {
    const float* x      = (const float*)d_in[0];
    const float* ew     = (const float*)d_in[1];
    const float* Wl0    = (const float*)d_in[2];
    const float* bl0    = (const float*)d_in[3];
    const float* Wr0    = (const float*)d_in[4];
    const float* br0    = (const float*)d_in[5];
    const float* We0    = (const float*)d_in[6];
    const float* att0   = (const float*)d_in[7];
    const float* bias0  = (const float*)d_in[8];
    const float* Wl1    = (const float*)d_in[9];
    const float* bl1    = (const float*)d_in[10];
    const float* Wr1    = (const float*)d_in[11];
    const float* br1    = (const float*)d_in[12];
    const float* We1    = (const float*)d_in[13];
    const float* att1   = (const float*)d_in[14];
    const float* bias1  = (const float*)d_in[15];
    const float* skipW  = (const float*)d_in[16];
    const float* skipb  = (const float*)d_in[17];
    const float* prelu0 = (const float*)d_in[18];
    const float* prelu1 = (const float*)d_in[19];
    const int*   eidx   = (const int*)d_in[20];
    float* out = (float*)d_out;

    float *xlr0p, *xlr1p, *skpp;
    uint32_t *xh, *xlo, *h0h, *h0l;
    uint32_t *wl0h, *wl0l, *wr0h, *wr0l, *wl1h, *wl1l, *wr1h, *wr1l, *wsh, *wsl;
    cudaGetSymbolAddress((void**)&xlr0p, d_xlr0);
    cudaGetSymbolAddress((void**)&xlr1p, d_xlr1);
    cudaGetSymbolAddress((void**)&skpp,  d_skp);
    cudaGetSymbolAddress((void**)&xh,  d_xh);
    cudaGetSymbolAddress((void**)&xlo, d_xlo);
    cudaGetSymbolAddress((void**)&h0h, d_h0h);
    cudaGetSymbolAddress((void**)&h0l, d_h0l);
    cudaGetSymbolAddress((void**)&wl0h, d_Wl0h); cudaGetSymbolAddress((void**)&wl0l, d_Wl0l);
    cudaGetSymbolAddress((void**)&wr0h, d_Wr0h); cudaGetSymbolAddress((void**)&wr0l, d_Wr0l);
    cudaGetSymbolAddress((void**)&wl1h, d_Wl1h); cudaGetSymbolAddress((void**)&wl1l, d_Wl1l);
    cudaGetSymbolAddress((void**)&wr1h, d_Wr1h); cudaGetSymbolAddress((void**)&wr1l, d_Wr1l);
    cudaGetSymbolAddress((void**)&wsh,  d_Wsh);  cudaGetSymbolAddress((void**)&wsl,  d_Wsl);

    cudaFuncSetAttribute(gemm_bf16x3, cudaFuncAttributeMaxDynamicSharedMemorySize, GEMM_DSMEM);

    const int MB = (NN + 127) / 128;  // 79

    // launches 1-3: operand splits for layer 0 (so launch 4 = big GEMM -> ncu target)
    {
        int nw = NN * IND / 2;
        split_rows_kernel<<<(nw + 255) / 256, 256>>>(x, xh, xlo, nw);
    }
    split_B_kernel<<<(IND / 2 * H0D + 255) / 256, 256>>>(Wl0, wl0h, wl0l, IND, H0D);
    split_B_kernel<<<(IND / 2 * H0D + 255) / 256, 256>>>(Wr0, wr0h, wr0l, IND, H0D);

    // launch 4: merged layer-0 projections x @ [Wl0|Wr0] -> d_xlr0 [NN][1024]
    gemm_bf16x3<<<dim3(1024 / 128, MB), 128, GEMM_DSMEM>>>(
        xh, xlo, wl0h, wl0l, wr0h, wr0l, bl0, br0, 512, xlr0p, NN, IND, 1024);

    // graph build (needed before gat0)
    zero_init_kernel<<<(NN + 255) / 256, 256>>>();
    hist_kernel<<<(EE + 255) / 256, 256>>>(eidx, ew);
    scan_kernel<<<1, 1024>>>();
    scatter_kernel<<<(ETOT + 255) / 256, 256>>>(eidx, ew);

    // remaining weight splits (independent; after gemm0 to keep launch-4 alignment)
    split_B_kernel<<<(H0D / 2 * EMBD + 255) / 256, 256>>>(Wl1, wl1h, wl1l, H0D, EMBD);
    split_B_kernel<<<(H0D / 2 * EMBD + 255) / 256, 256>>>(Wr1, wr1h, wr1l, H0D, EMBD);
    split_B_kernel<<<(IND / 2 * EMBD + 255) / 256, 256>>>(skipW, wsh, wsl, IND, EMBD);

    // layer 0 attention + aggregate + bias + PReLU (writes split h0)
    gat0_kernel<<<NN, 128>>>(We0, att0, bias0, prelu0);

    // merged layer-1 projections h0 @ [Wl1|Wr1] -> d_xlr1 [NN][512]
    gemm_bf16x3<<<dim3(512 / 128, MB), 128, GEMM_DSMEM>>>(
        h0h, h0l, wl1h, wl1l, wr1h, wr1l, bl1, br1, 256, xlr1p, NN, H0D, 512);

    // skip: x @ skipW -> d_skp [NN][256]
    gemm_bf16x3<<<dim3(256 / 128, MB), 128, GEMM_DSMEM>>>(
        xh, xlo, wsh, wsl, wsh, wsl, skipb, skipb, 256, skpp, NN, IND, 256);

    // layer 1 attention + aggregate + bias + skip + PReLU -> out
    gat1_kernel<<<(NN * 32 + 255) / 256, 256>>>(We1, att1, bias1, prelu1, out);

    (void)in_sizes; (void)n_in; (void)out_size;
}

// round 12
// speedup vs baseline: 2.1695x; 1.0424x over previous
#include <cuda_runtime.h>
#include <cstdint>

#define NN   10000
#define EE   160000
#define IND  256
#define H0D  512      // 4 heads * 128
#define EMBD 256
#define ETOT (EE + NN)
#define N0C  1280     // merged layer-0 output cols: xl0(512) | xr0(512) | skip(256)

// ---------------- scratch (device globals; no allocations allowed) ------------
__device__ float d_wsum[NN];
__device__ int   d_cnt[NN];
__device__ int   d_rowptr[NN + 1];
__device__ int   d_fill[NN];
__device__ int   d_csrc[ETOT];
__device__ float d_cw[ETOT];
__device__ __align__(16) float d_x0c [(size_t)NN * N0C];   // [xl0 | xr0 | skip]
__device__ __align__(16) float d_xlr1[(size_t)NN * 512];   // [xl1 | xr1]

// packed bf16x2 hi/lo operands
__device__ __align__(16) uint32_t d_xh [(size_t)NN * IND / 2];
__device__ __align__(16) uint32_t d_xlo[(size_t)NN * IND / 2];
__device__ __align__(16) uint32_t d_h0h[(size_t)NN * H0D / 2];
__device__ __align__(16) uint32_t d_h0l[(size_t)NN * H0D / 2];
__device__ __align__(16) uint32_t d_W0ch[(IND / 2) * N0C], d_W0cl[(IND / 2) * N0C];
__device__ __align__(16) uint32_t d_W1ch[(H0D / 2) * 512], d_W1cl[(H0D / 2) * 512];
__device__ float d_b0c[N0C];
__device__ float d_b1c[512];

// ---------------- bf16 split helpers -------------------------------------------
__device__ __forceinline__ uint32_t pack_bf2(float even_, float odd_) {
    uint32_t w;
    asm("cvt.rn.bf16x2.f32 %0, %1, %2;" : "=r"(w) : "f"(odd_), "f"(even_));
    return w;
}
__device__ __forceinline__ float bf_lo(uint32_t w) { return __uint_as_float(w << 16); }
__device__ __forceinline__ float bf_hi(uint32_t w) { return __uint_as_float(w & 0xffff0000u); }

__device__ __forceinline__ void split2(float f0, float f1, uint32_t& hi, uint32_t& lo) {
    hi = pack_bf2(f0, f1);
    lo = pack_bf2(f0 - bf_lo(hi), f1 - bf_hi(hi));
}

// launch 1: split x rows + assemble combined bias vectors
__global__ void split_x_bias(const float* __restrict__ x,
                             const float* __restrict__ bl0, const float* __restrict__ br0,
                             const float* __restrict__ skipb,
                             const float* __restrict__ bl1, const float* __restrict__ br1) {
    int i = blockIdx.x * blockDim.x + threadIdx.x;
    const int nw = NN * IND / 2;
    if (i < nw) {
        float2 f = ((const float2*)x)[i];
        uint32_t hi, lo;
        split2(f.x, f.y, hi, lo);
        d_xh[i] = hi; d_xlo[i] = lo;
    } else {
        int j = i - nw;
        if (j < 512)            d_b0c[j] = bl0[j];
        else if (j < 1024)      d_b0c[j] = br0[j - 512];
        else if (j < 1280)      d_b0c[j] = skipb[j - 1024];
        else if (j < 1280 + 256) d_b1c[j - 1280] = bl1[j - 1280];
        else if (j < 1280 + 512) d_b1c[j - 1280] = br1[j - 1536];
    }
}

// launch 2: split [Wl0|Wr0|skipW] -> combined [IND/2][1280]
__global__ void split_W0c(const float* __restrict__ Wl0, const float* __restrict__ Wr0,
                          const float* __restrict__ Ws) {
    int i = blockIdx.x * blockDim.x + threadIdx.x;
    const int total = (IND / 2) * N0C;
    if (i >= total) return;
    int k2 = i / N0C, n = i - k2 * N0C;
    const float* src; int scol, sN;
    if (n < 512)       { src = Wl0; scol = n;        sN = 512; }
    else if (n < 1024) { src = Wr0; scol = n - 512;  sN = 512; }
    else               { src = Ws;  scol = n - 1024; sN = 256; }
    float f0 = src[(size_t)(2 * k2) * sN + scol];
    float f1 = src[(size_t)(2 * k2 + 1) * sN + scol];
    uint32_t hi, lo;
    split2(f0, f1, hi, lo);
    d_W0ch[i] = hi; d_W0cl[i] = lo;
}

// launch 3: split [Wl1|Wr1] -> combined [H0D/2][512]
__global__ void split_W1c(const float* __restrict__ Wl1, const float* __restrict__ Wr1) {
    int i = blockIdx.x * blockDim.x + threadIdx.x;
    const int total = (H0D / 2) * 512;
    if (i >= total) return;
    int k2 = i / 512, n = i - k2 * 512;
    const float* src = (n < 256) ? Wl1 : Wr1;
    int scol = (n < 256) ? n : n - 256;
    float f0 = src[(size_t)(2 * k2) * EMBD + scol];
    float f1 = src[(size_t)(2 * k2 + 1) * EMBD + scol];
    uint32_t hi, lo;
    split2(f0, f1, hi, lo);
    d_W1ch[i] = hi; d_W1cl[i] = lo;
}

// ---------------- small utility kernels ---------------------------------------
__global__ void zero_init_kernel() {
    int i = blockIdx.x * blockDim.x + threadIdx.x;
    if (i < NN) { d_wsum[i] = 0.f; d_cnt[i] = 0; d_fill[i] = 0; }
}

__global__ void hist_kernel(const int* __restrict__ eidx, const float* __restrict__ ew) {
    int e = blockIdx.x * blockDim.x + threadIdx.x;
    if (e < EE) {
        int d = eidx[EE + e];
        atomicAdd(&d_cnt[d], 1);
        atomicAdd(&d_wsum[d], ew[e]);
    }
}

__global__ void scan_kernel() {
    __shared__ int sh[1024];
    const int CH = 10;
    int t = threadIdx.x;
    int base = t * CH;
    int loc[CH];
    int run = 0;
#pragma unroll
    for (int i = 0; i < CH; i++) {
        int idx = base + i;
        int c = (idx < NN) ? (d_cnt[idx] + 1) : 0;
        run += c;
        loc[i] = run;
    }
    sh[t] = run;
    __syncthreads();
    for (int off = 1; off < 1024; off <<= 1) {
        int v = (t >= off) ? sh[t - off] : 0;
        __syncthreads();
        sh[t] += v;
        __syncthreads();
    }
    int excl = sh[t] - run;
#pragma unroll
    for (int i = 0; i < CH; i++) {
        int idx = base + i;
        if (idx < NN) d_rowptr[idx + 1] = excl + loc[i];
    }
    if (t == 0) d_rowptr[0] = 0;
}

__global__ void scatter_kernel(const int* __restrict__ eidx, const float* __restrict__ ew) {
    int e = blockIdx.x * blockDim.x + threadIdx.x;
    if (e >= ETOT) return;
    int s, d; float w;
    if (e < EE) {
        s = eidx[e]; d = eidx[EE + e]; w = ew[e];
    } else {
        int n = e - EE;
        s = n; d = n;
        int c = d_cnt[n];
        w = (c > 0) ? (d_wsum[n] / (float)c) : 0.f;
    }
    int pos = d_rowptr[d] + atomicAdd(&d_fill[d], 1);
    d_csrc[pos] = s;
    d_cw[pos]   = w;
}

// ---------------- bf16x3 tensor-core GEMM (cp.async 3-stage, 3 CTA/SM) ---------
// C[M,N] = A[M,K] @ B[K,N] + bias[N]; hi*hi + lo*hi + hi*lo.
// BM=128, BN=128, BK=16, 128 threads (4 warps 2x2), warp tile 64x64.

__device__ __forceinline__ void mma16(float* c, const uint32_t* a, const uint32_t* b) {
    asm volatile(
        "mma.sync.aligned.m16n8k16.row.col.f32.bf16.bf16.f32 "
        "{%0,%1,%2,%3}, {%4,%5,%6,%7}, {%8,%9}, {%0,%1,%2,%3};"
        : "+f"(c[0]), "+f"(c[1]), "+f"(c[2]), "+f"(c[3])
        : "r"(a[0]), "r"(a[1]), "r"(a[2]), "r"(a[3]), "r"(b[0]), "r"(b[1]));
}

#define CP16(dst, src) \
    asm volatile("cp.async.cg.shared.global [%0], [%1], 16;" :: "r"(dst), "l"(src))
#define CP_COMMIT() asm volatile("cp.async.commit_group;" ::: "memory")
#define CP_WAIT(n)  asm volatile("cp.async.wait_group %0;" :: "n"(n) : "memory")

// stage layout (bytes): A-hi 128 rows x 12-word stride = 6144, A-lo 6144,
// B-hi 8 rows x 136-word stride = 4352, B-lo 4352
#define NSTG     3
#define ST_AH    0
#define ST_AL    6144
#define ST_BH    12288
#define ST_BL    16640
#define ST_BYTES 20992
#define GEMM_DSMEM (NSTG * ST_BYTES)   // 62976
#define ARSTR 12
#define BRSTR 136

__global__ __launch_bounds__(128, 3)
void gemm_bf16x3(const uint32_t* __restrict__ Ah, const uint32_t* __restrict__ Al,
                 const uint32_t* __restrict__ Bh, const uint32_t* __restrict__ Bl,
                 const float* __restrict__ bias, float* __restrict__ C,
                 int M, int K, int N) {
    extern __shared__ char smem[];
    const uint32_t s32 = (uint32_t)__cvta_generic_to_shared(smem);

    const int tid  = threadIdx.x;
    const int warp = tid >> 5;
    const int lane = tid & 31;
    const int r = lane >> 2;
    const int q = lane & 3;

    const int warp_m = (warp & 1) * 64;
    const int warp_n = (warp >> 1) * 64;
    const int m0 = blockIdx.y * 128;
    const int n0 = blockIdx.x * 128;
    const int Kw = K >> 1;

    float acc[4][8][4];
#pragma unroll
    for (int i = 0; i < 4; i++)
#pragma unroll
        for (int j = 0; j < 8; j++)
#pragma unroll
            for (int k = 0; k < 4; k++) acc[i][j][k] = 0.f;

    int am = m0 + tid; if (am >= M) am = M - 1;   // clamp: extra rows never stored
    const int brow = tid >> 4;            // 0..7  (k2 row)
    const int bcw  = (tid & 15) * 8;      // 0..120 word col

    const uint32_t dA_h = s32 + ST_AH + tid * 48;
    const uint32_t dA_l = s32 + ST_AL + tid * 48;
    const uint32_t dB_h = s32 + ST_BH + brow * (BRSTR * 4) + (tid & 15) * 32;
    const uint32_t dB_l = s32 + ST_BL + brow * (BRSTR * 4) + (tid & 15) * 32;

    const int nstages = K >> 4;

    // issue cp.async for one k16 stage into ring slot st
    auto load_stage = [&](int st, int w0) {
        const uint32_t so = (uint32_t)(st * ST_BYTES);
        const uint32_t* ap  = Ah + (size_t)am * Kw + w0;
        const uint32_t* alp = Al + (size_t)am * Kw + w0;
        CP16(dA_h + so,      ap);
        CP16(dA_h + so + 16, ap + 4);
        CP16(dA_l + so,      alp);
        CP16(dA_l + so + 16, alp + 4);
        const uint32_t* bp  = Bh + (size_t)(w0 + brow) * N + n0 + bcw;
        const uint32_t* blp = Bl + (size_t)(w0 + brow) * N + n0 + bcw;
        CP16(dB_h + so,      bp);
        CP16(dB_h + so + 16, bp + 4);
        CP16(dB_l + so,      blp);
        CP16(dB_l + so + 16, blp + 4);
    };

    // prologue: stages 0..NSTG-2
#pragma unroll
    for (int s = 0; s < NSTG - 1; s++) {
        if (s < nstages) load_stage(s, s * 8);
        CP_COMMIT();
    }

    for (int st = 0; st < nstages; st++) {
        CP_WAIT(NSTG - 2);       // stage st arrived
        __syncthreads();         // + everyone done computing stage st-1

        const int nxt = st + NSTG - 1;
        if (nxt < nstages) load_stage(nxt % NSTG, nxt * 8);
        CP_COMMIT();

        const int buf = st % NSTG;
        const uint32_t* Ash = (const uint32_t*)(smem + buf * ST_BYTES + ST_AH);
        const uint32_t* Asl = (const uint32_t*)(smem + buf * ST_BYTES + ST_AL);
        const uint32_t* Bsh = (const uint32_t*)(smem + buf * ST_BYTES + ST_BH);
        const uint32_t* Bsl = (const uint32_t*)(smem + buf * ST_BYTES + ST_BL);

        // B fragments for this stage (8 n-tiles, hi+lo)
        uint32_t bh[8][2], bl[8][2];
#pragma unroll
        for (int nt = 0; nt < 8; nt++) {
            const int nn = warp_n + nt * 8 + r;
            bh[nt][0] = Bsh[q * BRSTR + nn];
            bh[nt][1] = Bsh[(q + 4) * BRSTR + nn];
            bl[nt][0] = Bsl[q * BRSTR + nn];
            bl[nt][1] = Bsl[(q + 4) * BRSTR + nn];
        }

        // stream A fragments per m-tile; 24 MMAs each
#pragma unroll
        for (int mt = 0; mt < 4; mt++) {
            const int mm = warp_m + mt * 16 + r;
            uint32_t ah[4], al[4];
            ah[0] = Ash[mm * ARSTR + q];
            ah[1] = Ash[(mm + 8) * ARSTR + q];
            ah[2] = Ash[mm * ARSTR + q + 4];
            ah[3] = Ash[(mm + 8) * ARSTR + q + 4];
            al[0] = Asl[mm * ARSTR + q];
            al[1] = Asl[(mm + 8) * ARSTR + q];
            al[2] = Asl[mm * ARSTR + q + 4];
            al[3] = Asl[(mm + 8) * ARSTR + q + 4];
#pragma unroll
            for (int nt = 0; nt < 8; nt++) {
                mma16(acc[mt][nt], ah, bh[nt]);
                mma16(acc[mt][nt], al, bh[nt]);
                mma16(acc[mt][nt], ah, bl[nt]);
            }
        }
    }

    // epilogue: C[m][n] = acc + bias[n]
#pragma unroll
    for (int mt = 0; mt < 4; mt++) {
#pragma unroll
        for (int nt = 0; nt < 8; nt++) {
            const int col = n0 + warp_n + nt * 8 + 2 * q;
            const float bx = bias[col];
            const float by = bias[col + 1];
            const int row0 = m0 + warp_m + mt * 16 + r;
            const int row1 = row0 + 8;
            if (row0 < M) {
                float2 v = make_float2(acc[mt][nt][0] + bx, acc[mt][nt][1] + by);
                *(float2*)(C + (size_t)row0 * N + col) = v;
            }
            if (row1 < M) {
                float2 v = make_float2(acc[mt][nt][2] + bx, acc[mt][nt][3] + by);
                *(float2*)(C + (size_t)row1 * N + col) = v;
            }
        }
    }
}

// ---------------- GAT layer 0: 4 heads x 128, block per node -------------------
__device__ __forceinline__ float lrelu(float v) { return v >= 0.f ? v : 0.2f * v; }

__global__ __launch_bounds__(128)
void gat0_kernel(const float* __restrict__ We0, const float* __restrict__ att0,
                 const float* __restrict__ bias0, const float* __restrict__ prelu0) {
    int n = blockIdx.x;
    int lane = threadIdx.x & 31;
    int h = threadIdx.x >> 5;
    int c = h * 128 + lane * 4;

    float4 we = *(const float4*)(We0 + c);
    float4 at = *(const float4*)(att0 + c);
    float4 xr = *(const float4*)(d_x0c + (size_t)n * N0C + 512 + c);

    int rs = d_rowptr[n], re = d_rowptr[n + 1];
    float m = -1e30f, s = 0.f;
    float4 acc = make_float4(0.f, 0.f, 0.f, 0.f);

    for (int e = rs; e < re; e++) {
        int src = d_csrc[e];
        float w = d_cw[e];
        float4 xl = *(const float4*)(d_x0c + (size_t)src * N0C + c);
        float vx = lrelu(xl.x + xr.x + w * we.x);
        float vy = lrelu(xl.y + xr.y + w * we.y);
        float vz = lrelu(xl.z + xr.z + w * we.z);
        float vw = lrelu(xl.w + xr.w + w * we.w);
        float part = vx * at.x + vy * at.y + vz * at.z + vw * at.w;
#pragma unroll
        for (int off = 16; off; off >>= 1)
            part += __shfl_xor_sync(0xffffffffu, part, off);
        float nm = fmaxf(m, part);
        float corr = __expf(m - nm);
        float p = __expf(part - nm);
        s = s * corr + p;
        acc.x = acc.x * corr + p * xl.x;
        acc.y = acc.y * corr + p * xl.y;
        acc.z = acc.z * corr + p * xl.z;
        acc.w = acc.w * corr + p * xl.w;
        m = nm;
    }
    float inv = 1.f / (s + 1e-16f);
    float4 b = *(const float4*)(bias0 + c);
    float4 pr = *(const float4*)(prelu0 + c);
    float ox = acc.x * inv + b.x; ox = ox >= 0.f ? ox : pr.x * ox;
    float oy = acc.y * inv + b.y; oy = oy >= 0.f ? oy : pr.y * oy;
    float oz = acc.z * inv + b.z; oz = oz >= 0.f ? oz : pr.z * oz;
    float ow = acc.w * inv + b.w; ow = ow >= 0.f ? ow : pr.w * ow;

    // write h0 directly in split bf16 hi/lo packed form (layer-1 A operand)
    uint32_t w0h, w0l, w1h, w1l;
    split2(ox, oy, w0h, w0l);
    split2(oz, ow, w1h, w1l);
    size_t widx = ((size_t)n * H0D + c) >> 1;
    *(uint2*)(d_h0h + widx) = make_uint2(w0h, w1h);
    *(uint2*)(d_h0l + widx) = make_uint2(w0l, w1l);
}

// ---------------- GAT layer 1: 1 head x 256, warp per node ---------------------
__global__ __launch_bounds__(256)
void gat1_kernel(const float* __restrict__ We1, const float* __restrict__ att1,
                 const float* __restrict__ bias1, const float* __restrict__ prelu1,
                 float* __restrict__ out) {
    int gw = (blockIdx.x * blockDim.x + threadIdx.x) >> 5;
    if (gw >= NN) return;
    int n = gw;
    int lane = threadIdx.x & 31;
    int c0 = lane * 4, c1 = 128 + lane * 4;

    float4 weA = *(const float4*)(We1 + c0);
    float4 weB = *(const float4*)(We1 + c1);
    float4 atA = *(const float4*)(att1 + c0);
    float4 atB = *(const float4*)(att1 + c1);
    float4 xrA = *(const float4*)(d_xlr1 + (size_t)n * 512 + 256 + c0);
    float4 xrB = *(const float4*)(d_xlr1 + (size_t)n * 512 + 256 + c1);

    int rs = d_rowptr[n], re = d_rowptr[n + 1];
    float m = -1e30f, s = 0.f;
    float4 accA = make_float4(0.f, 0.f, 0.f, 0.f);
    float4 accB = make_float4(0.f, 0.f, 0.f, 0.f);

    for (int e = rs; e < re; e++) {
        int src = d_csrc[e];
        float w = d_cw[e];
        float4 xlA = *(const float4*)(d_xlr1 + (size_t)src * 512 + c0);
        float4 xlB = *(const float4*)(d_xlr1 + (size_t)src * 512 + c1);
        float part =
            lrelu(xlA.x + xrA.x + w * weA.x) * atA.x +
            lrelu(xlA.y + xrA.y + w * weA.y) * atA.y +
            lrelu(xlA.z + xrA.z + w * weA.z) * atA.z +
            lrelu(xlA.w + xrA.w + w * weA.w) * atA.w +
            lrelu(xlB.x + xrB.x + w * weB.x) * atB.x +
            lrelu(xlB.y + xrB.y + w * weB.y) * atB.y +
            lrelu(xlB.z + xrB.z + w * weB.z) * atB.z +
            lrelu(xlB.w + xrB.w + w * weB.w) * atB.w;
#pragma unroll
        for (int off = 16; off; off >>= 1)
            part += __shfl_xor_sync(0xffffffffu, part, off);
        float nm = fmaxf(m, part);
        float corr = __expf(m - nm);
        float p = __expf(part - nm);
        s = s * corr + p;
        accA.x = accA.x * corr + p * xlA.x;  accA.y = accA.y * corr + p * xlA.y;
        accA.z = accA.z * corr + p * xlA.z;  accA.w = accA.w * corr + p * xlA.w;
        accB.x = accB.x * corr + p * xlB.x;  accB.y = accB.y * corr + p * xlB.y;
        accB.z = accB.z * corr + p * xlB.z;  accB.w = accB.w * corr + p * xlB.w;
        m = nm;
    }
    float inv = 1.f / (s + 1e-16f);
    float4 bA = *(const float4*)(bias1 + c0);
    float4 bB = *(const float4*)(bias1 + c1);
    float4 pA = *(const float4*)(prelu1 + c0);
    float4 pB = *(const float4*)(prelu1 + c1);
    float4 skA = *(const float4*)(d_x0c + (size_t)n * N0C + 1024 + c0);
    float4 skB = *(const float4*)(d_x0c + (size_t)n * N0C + 1024 + c1);

    float o;
    float4 rA, rB;
    o = accA.x * inv + bA.x + skA.x; rA.x = o >= 0.f ? o : pA.x * o;
    o = accA.y * inv + bA.y + skA.y; rA.y = o >= 0.f ? o : pA.y * o;
    o = accA.z * inv + bA.z + skA.z; rA.z = o >= 0.f ? o : pA.z * o;
    o = accA.w * inv + bA.w + skA.w; rA.w = o >= 0.f ? o : pA.w * o;
    o = accB.x * inv + bB.x + skB.x; rB.x = o >= 0.f ? o : pB.x * o;
    o = accB.y * inv + bB.y + skB.y; rB.y = o >= 0.f ? o : pB.y * o;
    o = accB.z * inv + bB.z + skB.z; rB.z = o >= 0.f ? o : pB.z * o;
    o = accB.w * inv + bB.w + skB.w; rB.w = o >= 0.f ? o : pB.w * o;
    *(float4*)(out + (size_t)n * EMBD + c0) = rA;
    *(float4*)(out + (size_t)n * EMBD + c1) = rB;
}

// ---------------- launch -------------------------------------------------------
extern "C" void kernel_launch(void* const* d_in, const int* in_sizes, int n_in,
                              void* d_out, int out_size) {
    const float* x      = (const float*)d_in[0];
    const float* ew     = (const float*)d_in[1];
    const float* Wl0    = (const float*)d_in[2];
    const float* bl0    = (const float*)d_in[3];
    const float* Wr0    = (const float*)d_in[4];
    const float* br0    = (const float*)d_in[5];
    const float* We0    = (const float*)d_in[6];
    const float* att0   = (const float*)d_in[7];
    const float* bias0  = (const float*)d_in[8];
    const float* Wl1    = (const float*)d_in[9];
    const float* bl1    = (const float*)d_in[10];
    const float* Wr1    = (const float*)d_in[11];
    const float* br1    = (const float*)d_in[12];
    const float* We1    = (const float*)d_in[13];
    const float* att1   = (const float*)d_in[14];
    const float* bias1  = (const float*)d_in[15];
    const float* skipW  = (const float*)d_in[16];
    const float* skipb  = (const float*)d_in[17];
    const float* prelu0 = (const float*)d_in[18];
    const float* prelu1 = (const float*)d_in[19];
    const int*   eidx   = (const int*)d_in[20];
    float* out = (float*)d_out;

    float *x0cp, *xlr1p, *b0cp, *b1cp;
    uint32_t *xh, *xlo, *h0h, *h0l, *w0ch, *w0cl, *w1ch, *w1cl;
    cudaGetSymbolAddress((void**)&x0cp,  d_x0c);
    cudaGetSymbolAddress((void**)&xlr1p, d_xlr1);
    cudaGetSymbolAddress((void**)&b0cp,  d_b0c);
    cudaGetSymbolAddress((void**)&b1cp,  d_b1c);
    cudaGetSymbolAddress((void**)&xh,  d_xh);
    cudaGetSymbolAddress((void**)&xlo, d_xlo);
    cudaGetSymbolAddress((void**)&h0h, d_h0h);
    cudaGetSymbolAddress((void**)&h0l, d_h0l);
    cudaGetSymbolAddress((void**)&w0ch, d_W0ch); cudaGetSymbolAddress((void**)&w0cl, d_W0cl);
    cudaGetSymbolAddress((void**)&w1ch, d_W1ch); cudaGetSymbolAddress((void**)&w1cl, d_W1cl);

    cudaFuncSetAttribute(gemm_bf16x3, cudaFuncAttributeMaxDynamicSharedMemorySize, GEMM_DSMEM);

    const int MB = (NN + 127) / 128;  // 79

    // launches 1-3: operand splits (so launch 4 = big GEMM -> ncu capture target)
    {
        int tot = NN * IND / 2 + N0C + 512;
        split_x_bias<<<(tot + 255) / 256, 256>>>(x, bl0, br0, skipb, bl1, br1);
    }
    split_W0c<<<((IND / 2) * N0C + 255) / 256, 256>>>(Wl0, Wr0, skipW);
    split_W1c<<<((H0D / 2) * 512 + 255) / 256, 256>>>(Wl1, Wr1);

    // launch 4: merged x @ [Wl0|Wr0|skipW] -> d_x0c [NN][1280]
    gemm_bf16x3<<<dim3(N0C / 128, MB), 128, GEMM_DSMEM>>>(
        xh, xlo, w0ch, w0cl, b0cp, x0cp, NN, IND, N0C);

    // graph build (needed before gat0)
    zero_init_kernel<<<(NN + 255) / 256, 256>>>();
    hist_kernel<<<(EE + 255) / 256, 256>>>(eidx, ew);
    scan_kernel<<<1, 1024>>>();
    scatter_kernel<<<(ETOT + 255) / 256, 256>>>(eidx, ew);

    // layer 0 attention + aggregate + bias + PReLU (writes split h0)
    gat0_kernel<<<NN, 128>>>(We0, att0, bias0, prelu0);

    // merged layer-1 projections h0 @ [Wl1|Wr1] -> d_xlr1 [NN][512]
    gemm_bf16x3<<<dim3(512 / 128, MB), 128, GEMM_DSMEM>>>(
        h0h, h0l, w1ch, w1cl, b1cp, xlr1p, NN, H0D, 512);

    // layer 1 attention + aggregate + bias + skip + PReLU -> out
    gat1_kernel<<<(NN * 32 + 255) / 256, 256>>>(We1, att1, bias1, prelu1, out);

    (void)in_sizes; (void)n_in; (void)out_size;
}